// round 12
// baseline (speedup 1.0000x reference)
#include <cuda_runtime.h>
#include <cstdint>
#include <math.h>

// Problem constants
#define S_DIM 256
#define CH    32          // head dim
#define NH    8           // heads
#define CIN   128         // input channels
#define CQK   256         // NH*CH
#define NROWS (S_DIM * S_DIM)

typedef unsigned long long ull;

// ---------------------------------------------------------------------------
// Packed f32x2 helpers (sm_103a FFMA2 path — PTX-only)
// ---------------------------------------------------------------------------
__device__ __forceinline__ ull pk2(float lo, float hi) {
    ull r; asm("mov.b64 %0, {%1, %2};" : "=l"(r) : "f"(lo), "f"(hi)); return r;
}
__device__ __forceinline__ float2 upk2(ull v) {
    float lo, hi; asm("mov.b64 {%0, %1}, %2;" : "=f"(lo), "=f"(hi) : "l"(v));
    return make_float2(lo, hi);
}
__device__ __forceinline__ ull fma2(ull a, ull b, ull c) {
    ull d; asm("fma.rn.f32x2 %0, %1, %2, %3;" : "=l"(d) : "l"(a), "l"(b), "l"(c)); return d;
}

// ---------------------------------------------------------------------------
// Scratch
// ---------------------------------------------------------------------------
__device__ float g_Q[(size_t)NROWS * CQK];
__device__ float g_K[(size_t)NROWS * CQK];
__device__ float g_V[(size_t)NROWS * CQK];
__device__ float g_G[(size_t)NROWS * CQK];
__device__ float g_O[(size_t)NROWS * CQK];
__device__ int   g_mask_code;   // 0=int32, 1=uint8, 2=float32

// ---------------------------------------------------------------------------
// Mask dtype detection
// ---------------------------------------------------------------------------
__global__ void detect_mask_kernel(const unsigned char* __restrict__ m, int nbytes)
{
    __shared__ int f_float, f_u8;
    if (threadIdx.x == 0) { f_float = 0; f_u8 = 0; }
    __syncthreads();
    int lf = 0, lu = 0;
    for (int i = threadIdx.x; i < nbytes; i += blockDim.x) {
        unsigned char v = m[i];
        if (v >= 2) lf = 1;
        if ((i & 3) && v) lu = 1;
    }
    if (lf) atomicOr(&f_float, 1);
    if (lu) atomicOr(&f_u8, 1);
    __syncthreads();
    if (threadIdx.x == 0)
        g_mask_code = f_float ? 2 : (f_u8 ? 1 : 0);
}

// ---------------------------------------------------------------------------
// fp32 SGEMM v7: 128x128 tile, BK=16, 256 threads, FFMA2 2x2 blocks of 4x4
// microtile. A stored in smem as PRE-DUPLICATED (a,a) 8-byte pairs ->
// zero packing MOVs in the inner loop (4 broadcast LDS.128 for A).
// B loads conflict-free (split 4-wide column groups). Double-buffered.
//   mode 0: none / 1: C*=scale / 2: sigmoid(C+evec) / 3: C+evec
// ---------------------------------------------------------------------------
#define GBM 128
#define GBN 128
#define GBK 16

__global__ __launch_bounds__(256, 2)
void sgemm7(const float* __restrict__ A, const float* __restrict__ B,
            float* __restrict__ C, int M, int N, int K,
            int mode, const float* __restrict__ evec, float scale)
{
    __shared__ ull   Asd[2][GBK * GBM];   // duplicated pairs: 16KB/buffer
    __shared__ float Bs[2][GBK * GBN];    // 8KB/buffer

    const int t  = threadIdx.x;
    const int bm = blockIdx.y * GBM;
    const int bn = blockIdx.x * GBN;

    // A loader: 128 rows x 16 k; 2 threads/row, 8 k each
    const int arow = t >> 1;
    const int ak   = (t & 1) * 8;
    // B loader: 16 rows x 128 cols; 8 cols each
    const int brow = t >> 4;
    const int bcol = (t & 15) * 8;

    const int tx = t & 15;
    const int ty = t >> 4;

    ull acc2[8][4];
#pragma unroll
    for (int i = 0; i < 8; i++)
#pragma unroll
        for (int j = 0; j < 4; j++) acc2[i][j] = 0ULL;

    {
        const float* arp = A + (size_t)(bm + arow) * K + ak;
        float4 a0 = *(const float4*)arp;
        float4 a1 = *(const float4*)(arp + 4);
        Asd[0][(ak + 0) * GBM + arow] = pk2(a0.x, a0.x);
        Asd[0][(ak + 1) * GBM + arow] = pk2(a0.y, a0.y);
        Asd[0][(ak + 2) * GBM + arow] = pk2(a0.z, a0.z);
        Asd[0][(ak + 3) * GBM + arow] = pk2(a0.w, a0.w);
        Asd[0][(ak + 4) * GBM + arow] = pk2(a1.x, a1.x);
        Asd[0][(ak + 5) * GBM + arow] = pk2(a1.y, a1.y);
        Asd[0][(ak + 6) * GBM + arow] = pk2(a1.z, a1.z);
        Asd[0][(ak + 7) * GBM + arow] = pk2(a1.w, a1.w);
        *(float4*)&Bs[0][brow * GBN + bcol] =
            *(const float4*)(B + (size_t)brow * N + bn + bcol);
        *(float4*)&Bs[0][brow * GBN + bcol + 4] =
            *(const float4*)(B + (size_t)brow * N + bn + bcol + 4);
    }
    __syncthreads();

    int p = 0;
    for (int k0 = 0; k0 < K; k0 += GBK) {
        const bool has_next = (k0 + GBK) < K;
        float4 a0g, a1g, b0g, b1g;
        if (has_next) {
            const float* arp = A + (size_t)(bm + arow) * K + k0 + GBK + ak;
            a0g = *(const float4*)arp;
            a1g = *(const float4*)(arp + 4);
            b0g = *(const float4*)(B + (size_t)(k0 + GBK + brow) * N + bn + bcol);
            b1g = *(const float4*)(B + (size_t)(k0 + GBK + brow) * N + bn + bcol + 4);
        }

        const ull*   Asp = Asd[p];
        const float* Bsp = Bs[p];
#pragma unroll
        for (int kk = 0; kk < GBK; kk++) {
            ulonglong2 aA = *(const ulonglong2*)&Asp[kk * GBM + ty * 4];        // bcast
            ulonglong2 aB = *(const ulonglong2*)&Asp[kk * GBM + ty * 4 + 2];    // bcast
            ulonglong2 aC = *(const ulonglong2*)&Asp[kk * GBM + 64 + ty * 4];   // bcast
            ulonglong2 aD = *(const ulonglong2*)&Asp[kk * GBM + 64 + ty * 4 + 2];
            ulonglong2 b0 = *(const ulonglong2*)&Bs[p][kk * GBN + tx * 4];      // CF
            ulonglong2 b1 = *(const ulonglong2*)&Bs[p][kk * GBN + 64 + tx * 4]; // CF
            ull aa[8] = {aA.x, aA.y, aB.x, aB.y, aC.x, aC.y, aD.x, aD.y};
            ull b2[4] = {b0.x, b0.y, b1.x, b1.y};
#pragma unroll
            for (int i = 0; i < 8; i++)
#pragma unroll
                for (int j = 0; j < 4; j++)
                    acc2[i][j] = fma2(aa[i], b2[j], acc2[i][j]);
        }

        if (has_next) {
            const int q = p ^ 1;
            Asd[q][(ak + 0) * GBM + arow] = pk2(a0g.x, a0g.x);
            Asd[q][(ak + 1) * GBM + arow] = pk2(a0g.y, a0g.y);
            Asd[q][(ak + 2) * GBM + arow] = pk2(a0g.z, a0g.z);
            Asd[q][(ak + 3) * GBM + arow] = pk2(a0g.w, a0g.w);
            Asd[q][(ak + 4) * GBM + arow] = pk2(a1g.x, a1g.x);
            Asd[q][(ak + 5) * GBM + arow] = pk2(a1g.y, a1g.y);
            Asd[q][(ak + 6) * GBM + arow] = pk2(a1g.z, a1g.z);
            Asd[q][(ak + 7) * GBM + arow] = pk2(a1g.w, a1g.w);
            *(float4*)&Bs[q][brow * GBN + bcol] = b0g;
            *(float4*)&Bs[q][brow * GBN + bcol + 4] = b1g;
            __syncthreads();
            p = q;
        }
    }

#pragma unroll
    for (int i = 0; i < 8; i++) {
        const int row = bm + ((i < 4) ? (ty * 4 + i) : (64 + ty * 4 + i - 4));
        float vlo[4], vhi[4];
        {
            float2 v0 = upk2(acc2[i][0]);
            float2 v1 = upk2(acc2[i][1]);
            vlo[0] = v0.x; vlo[1] = v0.y; vlo[2] = v1.x; vlo[3] = v1.y;
            float2 v2 = upk2(acc2[i][2]);
            float2 v3 = upk2(acc2[i][3]);
            vhi[0] = v2.x; vhi[1] = v2.y; vhi[2] = v3.x; vhi[3] = v3.y;
        }
#pragma unroll
        for (int j = 0; j < 4; j++) {
            const int clo = bn + tx * 4 + j;
            const int chi = bn + 64 + tx * 4 + j;
            float zl = vlo[j], zh = vhi[j];
            if (mode == 1)      { zl *= scale; zh *= scale; }
            else if (mode == 2) {
                zl = 1.f / (1.f + __expf(-(zl + evec[clo])));
                zh = 1.f / (1.f + __expf(-(zh + evec[chi])));
            }
            else if (mode == 3) { zl += evec[clo]; zh += evec[chi]; }
            vlo[j] = zl; vhi[j] = zh;
        }
        *(float4*)(C + (size_t)row * N + bn + tx * 4) =
            make_float4(vlo[0], vlo[1], vlo[2], vlo[3]);
        *(float4*)(C + (size_t)row * N + bn + 64 + tx * 4) =
            make_float4(vhi[0], vhi[1], vhi[2], vhi[3]);
    }
}

// ---------------------------------------------------------------------------
// Attention v5 (revert to round-9 best, 640us): 128-q blocks, 256 threads,
// fused in-register shfl softmax, normalized P, 2 barriers.
// ---------------------------------------------------------------------------
#define LSTR 268
#define OFF_KS   34304
#define OFF_QS   42496
#define OFF_VS   46592
#define OFF_ADDM 54784
#define ATTN_SMEM_BYTES (55040 * 4)

__global__ __launch_bounds__(256, 1)
void attn5(const float* __restrict__ Q, const float* __restrict__ Km,
           const float* __restrict__ V, const float* __restrict__ G,
           const float* __restrict__ bias, const void* __restrict__ mask,
           float* __restrict__ O)
{
    extern __shared__ float sm[];
    float* L    = sm;                 // normalized P after pass 1
    float* Ks   = sm + OFF_KS;
    float* Qs   = sm + OFF_QS;
    float* Vs   = sm + OFF_VS;
    float* addm = sm + OFF_ADDM;

    const int h  = blockIdx.x;
    const int s  = blockIdx.y;
    const int qh = blockIdx.z;
    const int t  = threadIdx.x;

    // ---- stage Q transposed: Qs[c][q] ----
    {
        const int q = t >> 1, c0 = (t & 1) * 16;
        const float4* src = (const float4*)(Q + ((size_t)(s * S_DIM + qh * 128 + q)) * CQK + h * CH + c0);
#pragma unroll
        for (int j = 0; j < 4; j++) {
            float4 v = src[j];
            Qs[(c0 + 4 * j + 0) * 128 + q] = v.x;
            Qs[(c0 + 4 * j + 1) * 128 + q] = v.y;
            Qs[(c0 + 4 * j + 2) * 128 + q] = v.z;
            Qs[(c0 + 4 * j + 3) * 128 + q] = v.w;
        }
    }
    // ---- stage K transposed: Ks[c][k] ----
    {
        const int k = t;
        const float4* src = (const float4*)(Km + ((size_t)(s * S_DIM + k)) * CQK + h * CH);
#pragma unroll
        for (int j = 0; j < 8; j++) {
            float4 v = src[j];
            Ks[(4 * j + 0) * S_DIM + k] = v.x;
            Ks[(4 * j + 1) * S_DIM + k] = v.y;
            Ks[(4 * j + 2) * S_DIM + k] = v.z;
            Ks[(4 * j + 3) * S_DIM + k] = v.w;
        }
    }
    // ---- stage V natural [k][c] + mask ----
    {
        const float4* Vg4 = (const float4*)V;
        const size_t rowbase = ((size_t)s * S_DIM) * (CQK / 4) + h * (CH / 4);
#pragma unroll
        for (int f = t; f < S_DIM * (CH / 4); f += 256) {
            int k = f >> 3, c4 = f & 7;
            ((float4*)Vs)[k * 8 + c4] = Vg4[rowbase + (size_t)k * (CQK / 4) + c4];
        }
        const int idx = s * S_DIM + t;
        const int code = g_mask_code;
        bool mv;
        if (code == 2)      mv = ((const float*)mask)[idx] != 0.f;
        else if (code == 1) mv = ((const unsigned char*)mask)[idx] != 0;
        else                mv = ((const int*)mask)[idx] != 0;
        addm[t] = mv ? 0.f : -1e30f;
    }
    __syncthreads();

    // ---- pass 1 + fused softmax ----
    const float* brow = bias + ((size_t)(h * S_DIM + qh * 128)) * S_DIM;
#pragma unroll
    for (int rep = 0; rep < 2; rep++) {
        const int tile = t + rep * 256;
        const int qi = tile >> 5, ki = tile & 31;   // qi warp-uniform
        const int q0 = qi * 8;
        const int kA = ki * 4, kB = 128 + ki * 4;

        ull acc2[8][4];
#pragma unroll
        for (int i = 0; i < 8; i++)
#pragma unroll
            for (int j = 0; j < 4; j++) acc2[i][j] = 0ULL;

#pragma unroll 2
        for (int c = 0; c < CH; c++) {
            float4 qa = *(const float4*)&Qs[c * 128 + q0];        // broadcast
            float4 qb = *(const float4*)&Qs[c * 128 + q0 + 4];    // broadcast
            ulonglong2 k0v = *(const ulonglong2*)&Ks[c * S_DIM + kA];  // CF
            ulonglong2 k1v = *(const ulonglong2*)&Ks[c * S_DIM + kB];  // CF
            ull b2[4] = {k0v.x, k0v.y, k1v.x, k1v.y};
            ull aa[8] = {pk2(qa.x, qa.x), pk2(qa.y, qa.y), pk2(qa.z, qa.z), pk2(qa.w, qa.w),
                         pk2(qb.x, qb.x), pk2(qb.y, qb.y), pk2(qb.z, qb.z), pk2(qb.w, qb.w)};
#pragma unroll
            for (int i = 0; i < 8; i++)
#pragma unroll
                for (int j = 0; j < 4; j++)
                    acc2[i][j] = fma2(aa[i], b2[j], acc2[i][j]);
        }

        // unpack + bias + mask into v[8][8]
        float v[8][8];
        {
            float4 amA = *(const float4*)&addm[kA];
            float4 amB = *(const float4*)&addm[kB];
#pragma unroll
            for (int i = 0; i < 8; i++) {
                const int q = q0 + i;
                float4 bbA = *(const float4*)(brow + (size_t)q * S_DIM + kA);
                float4 bbB = *(const float4*)(brow + (size_t)q * S_DIM + kB);
                float2 d0 = upk2(acc2[i][0]);
                float2 d1 = upk2(acc2[i][1]);
                float2 d2 = upk2(acc2[i][2]);
                float2 d3 = upk2(acc2[i][3]);
                v[i][0] = d0.x + bbA.x + amA.x;
                v[i][1] = d0.y + bbA.y + amA.y;
                v[i][2] = d1.x + bbA.z + amA.z;
                v[i][3] = d1.y + bbA.w + amA.w;
                v[i][4] = d2.x + bbB.x + amB.x;
                v[i][5] = d2.y + bbB.y + amB.y;
                v[i][6] = d3.x + bbB.z + amB.z;
                v[i][7] = d3.y + bbB.w + amB.w;
            }
        }

        // row max across warp (ILP-8 butterfly)
        float rm[8];
#pragma unroll
        for (int i = 0; i < 8; i++) {
            float m01 = fmaxf(fmaxf(v[i][0], v[i][1]), fmaxf(v[i][2], v[i][3]));
            float m23 = fmaxf(fmaxf(v[i][4], v[i][5]), fmaxf(v[i][6], v[i][7]));
            rm[i] = fmaxf(m01, m23);
        }
#pragma unroll
        for (int st = 16; st >= 1; st >>= 1)
#pragma unroll
            for (int i = 0; i < 8; i++)
                rm[i] = fmaxf(rm[i], __shfl_xor_sync(0xFFFFFFFFu, rm[i], st));

        // exp + row sum across warp
        float rs[8];
#pragma unroll
        for (int i = 0; i < 8; i++) {
            float s0 = 0.f;
#pragma unroll
            for (int j = 0; j < 8; j++) {
                v[i][j] = __expf(v[i][j] - rm[i]);
                s0 += v[i][j];
            }
            rs[i] = s0;
        }
#pragma unroll
        for (int st = 16; st >= 1; st >>= 1)
#pragma unroll
            for (int i = 0; i < 8; i++)
                rs[i] += __shfl_xor_sync(0xFFFFFFFFu, rs[i], st);

        // normalize + store P
#pragma unroll
        for (int i = 0; i < 8; i++) {
            const int q = q0 + i;
            const float riv = 1.f / rs[i];
            *(float4*)&L[q * LSTR + kA] = make_float4(
                v[i][0] * riv, v[i][1] * riv, v[i][2] * riv, v[i][3] * riv);
            *(float4*)&L[q * LSTR + kB] = make_float4(
                v[i][4] * riv, v[i][5] * riv, v[i][6] * riv, v[i][7] * riv);
        }
    }
    __syncthreads();

    // ---- pass 2: O = P.V, 4q x 4c per thread (P pre-normalized) ----
    {
        const int qi = t >> 3, ci = t & 7;
        const int q0 = qi * 4, c0 = ci * 4;
        ull acc2[4][2];
#pragma unroll
        for (int i = 0; i < 4; i++) { acc2[i][0] = 0ULL; acc2[i][1] = 0ULL; }

#pragma unroll 2
        for (int k0 = 0; k0 < S_DIM; k0 += 4) {
            ulonglong2 v0 = *(const ulonglong2*)&Vs[(k0 + 0) * CH + c0];
            ulonglong2 v1 = *(const ulonglong2*)&Vs[(k0 + 1) * CH + c0];
            ulonglong2 v2 = *(const ulonglong2*)&Vs[(k0 + 2) * CH + c0];
            ulonglong2 v3 = *(const ulonglong2*)&Vs[(k0 + 3) * CH + c0];
#pragma unroll
            for (int i = 0; i < 4; i++) {
                float4 pv = *(const float4*)&L[(q0 + i) * LSTR + k0];
                ull a0 = pk2(pv.x, pv.x);
                ull a1 = pk2(pv.y, pv.y);
                ull a2 = pk2(pv.z, pv.z);
                ull a3 = pk2(pv.w, pv.w);
                acc2[i][0] = fma2(a0, v0.x, acc2[i][0]);
                acc2[i][1] = fma2(a0, v0.y, acc2[i][1]);
                acc2[i][0] = fma2(a1, v1.x, acc2[i][0]);
                acc2[i][1] = fma2(a1, v1.y, acc2[i][1]);
                acc2[i][0] = fma2(a2, v2.x, acc2[i][0]);
                acc2[i][1] = fma2(a2, v2.y, acc2[i][1]);
                acc2[i][0] = fma2(a3, v3.x, acc2[i][0]);
                acc2[i][1] = fma2(a3, v3.y, acc2[i][1]);
            }
        }
#pragma unroll
        for (int i = 0; i < 4; i++) {
            const int q = q0 + i;
            const size_t row = (size_t)(s * S_DIM + qh * 128 + q);
            float4 gv = *(const float4*)(G + row * CQK + h * CH + c0);
            float2 x0 = upk2(acc2[i][0]);
            float2 x1 = upk2(acc2[i][1]);
            float4 ov;
            ov.x = x0.x * gv.x;
            ov.y = x0.y * gv.y;
            ov.z = x1.x * gv.z;
            ov.w = x1.y * gv.w;
            *(float4*)(O + row * CQK + h * CH + c0) = ov;
        }
    }
}

// ---------------------------------------------------------------------------
// Launch
// ---------------------------------------------------------------------------
extern "C" void kernel_launch(void* const* d_in, const int* in_sizes, int n_in,
                              void* d_out, int out_size)
{
    const float* x    = (const float*)d_in[0];
    const float* bias = (const float*)d_in[1];
    const void*  mask = d_in[2];
    const float* Wq   = (const float*)d_in[3];
    const float* Wk   = (const float*)d_in[4];
    const float* Wv   = (const float*)d_in[5];
    const float* Wo   = (const float*)d_in[6];
    const float* bo   = (const float*)d_in[7];
    const float* Wg   = (const float*)d_in[8];
    const float* bg   = (const float*)d_in[9];
    float* out = (float*)d_out;

    void *pQ, *pK, *pV, *pG, *pO;
    cudaGetSymbolAddress(&pQ, g_Q);
    cudaGetSymbolAddress(&pK, g_K);
    cudaGetSymbolAddress(&pV, g_V);
    cudaGetSymbolAddress(&pG, g_G);
    cudaGetSymbolAddress(&pO, g_O);
    float* Qb = (float*)pQ; float* Kb = (float*)pK; float* Vb = (float*)pV;
    float* Gb = (float*)pG; float* Ob = (float*)pO;

    const float qscale = 0.17677669529663687f;   // 1/sqrt(32)

    dim3 gproj(CQK / GBN, NROWS / GBM);   // (2, 512)
    sgemm7<<<gproj, 256>>>(x, Wq, Qb, NROWS, CQK, CIN, 1, nullptr, qscale);
    sgemm7<<<gproj, 256>>>(x, Wk, Kb, NROWS, CQK, CIN, 0, nullptr, 1.f);
    sgemm7<<<gproj, 256>>>(x, Wv, Vb, NROWS, CQK, CIN, 0, nullptr, 1.f);
    sgemm7<<<gproj, 256>>>(x, Wg, Gb, NROWS, CQK, CIN, 2, bg, 1.f);

    detect_mask_kernel<<<1, 256>>>((const unsigned char*)mask, S_DIM * S_DIM);

    cudaFuncSetAttribute(attn5, cudaFuncAttributeMaxDynamicSharedMemorySize, ATTN_SMEM_BYTES);
    attn5<<<dim3(NH, S_DIM, 2), 256, ATTN_SMEM_BYTES>>>(Qb, Kb, Vb, Gb, bias, mask, Ob);

    dim3 gout(CIN / GBN, NROWS / GBM);    // (1, 512)
    sgemm7<<<gout, 256>>>(Ob, Wo, out, NROWS, CIN, CQK, 3, bo, 1.f);
}

// round 13
// speedup vs baseline: 1.1635x; 1.1635x over previous
#include <cuda_runtime.h>
#include <cuda_fp16.h>
#include <cstdint>
#include <math.h>

// Problem constants
#define S_DIM 256
#define CH    32          // head dim
#define NH    8           // heads
#define CIN   128         // input channels
#define CQK   256         // NH*CH
#define NROWS (S_DIM * S_DIM)

typedef unsigned long long ull;

// ---------------------------------------------------------------------------
// Packed f32x2 helpers (sm_103a FFMA2 path — PTX-only)
// ---------------------------------------------------------------------------
__device__ __forceinline__ ull pk2(float lo, float hi) {
    ull r; asm("mov.b64 %0, {%1, %2};" : "=l"(r) : "f"(lo), "f"(hi)); return r;
}
__device__ __forceinline__ float2 upk2(ull v) {
    float lo, hi; asm("mov.b64 {%0, %1}, %2;" : "=f"(lo), "=f"(hi) : "l"(v));
    return make_float2(lo, hi);
}
__device__ __forceinline__ ull fma2(ull a, ull b, ull c) {
    ull d; asm("fma.rn.f32x2 %0, %1, %2, %3;" : "=l"(d) : "l"(a), "l"(b), "l"(c)); return d;
}

// ---------------------------------------------------------------------------
// Scratch
// ---------------------------------------------------------------------------
__device__ float g_Q[(size_t)NROWS * CQK];
__device__ float g_K[(size_t)NROWS * CQK];
__device__ float g_V[(size_t)NROWS * CQK];
__device__ float g_G[(size_t)NROWS * CQK];
__device__ float g_O[(size_t)NROWS * CQK];
__device__ int   g_mask_code;   // 0=int32, 1=uint8, 2=float32

// ---------------------------------------------------------------------------
// Mask dtype detection
// ---------------------------------------------------------------------------
__global__ void detect_mask_kernel(const unsigned char* __restrict__ m, int nbytes)
{
    __shared__ int f_float, f_u8;
    if (threadIdx.x == 0) { f_float = 0; f_u8 = 0; }
    __syncthreads();
    int lf = 0, lu = 0;
    for (int i = threadIdx.x; i < nbytes; i += blockDim.x) {
        unsigned char v = m[i];
        if (v >= 2) lf = 1;
        if ((i & 3) && v) lu = 1;
    }
    if (lf) atomicOr(&f_float, 1);
    if (lu) atomicOr(&f_u8, 1);
    __syncthreads();
    if (threadIdx.x == 0)
        g_mask_code = f_float ? 2 : (f_u8 ? 1 : 0);
}

// ---------------------------------------------------------------------------
// Fused Q/K/V/G projection GEMM (sgemm6 body): ONE launch, grid (8, 512).
// blockIdx.x: bit0 = n-half (0/1 -> cols 0..127 / 128..255), bits1-2 = weight.
// All four share A = x [65536,128]; B = W[128,256]; C row stride 256.
// Epilogue: w0 Q (scale), w1 K, w2 V, w3 G (sigmoid + bg).
// ---------------------------------------------------------------------------
#define GBM 128
#define GBK 16
#define FPN 256
#define FPK 128

__global__ __launch_bounds__(256, 2)
void fused_proj(const float* __restrict__ A,
                const float* __restrict__ Wq, const float* __restrict__ Wk,
                const float* __restrict__ Wv, const float* __restrict__ Wg,
                float* __restrict__ Qb, float* __restrict__ Kb,
                float* __restrict__ Vb, float* __restrict__ Gb,
                const float* __restrict__ bg, float qscale)
{
    __shared__ float As[2][GBK * GBM];
    __shared__ float Bs[2][GBK * GBM];   // 16 x 128 (this block's n-half)

    const int t  = threadIdx.x;
    const int w  = blockIdx.x >> 1;
    const int bn = (blockIdx.x & 1) * 128;
    const int bm = blockIdx.y * GBM;

    const float* B; float* C;
    if      (w == 0) { B = Wq; C = Qb; }
    else if (w == 1) { B = Wk; C = Kb; }
    else if (w == 2) { B = Wv; C = Vb; }
    else             { B = Wg; C = Gb; }

    const int arow = t >> 1;
    const int ak   = (t & 1) * 8;
    const int brow = t >> 4;
    const int bcol = (t & 15) * 8;

    const int tx = t & 15;
    const int ty = t >> 4;

    ull acc2[8][4];
#pragma unroll
    for (int i = 0; i < 8; i++)
#pragma unroll
        for (int j = 0; j < 4; j++) acc2[i][j] = 0ULL;

    {
        const float* arp = A + (size_t)(bm + arow) * FPK + ak;
        float4 a0 = *(const float4*)arp;
        float4 a1 = *(const float4*)(arp + 4);
        As[0][(ak + 0) * GBM + arow] = a0.x;
        As[0][(ak + 1) * GBM + arow] = a0.y;
        As[0][(ak + 2) * GBM + arow] = a0.z;
        As[0][(ak + 3) * GBM + arow] = a0.w;
        As[0][(ak + 4) * GBM + arow] = a1.x;
        As[0][(ak + 5) * GBM + arow] = a1.y;
        As[0][(ak + 6) * GBM + arow] = a1.z;
        As[0][(ak + 7) * GBM + arow] = a1.w;
        *(float4*)&Bs[0][brow * 128 + bcol] =
            *(const float4*)(B + (size_t)brow * FPN + bn + bcol);
        *(float4*)&Bs[0][brow * 128 + bcol + 4] =
            *(const float4*)(B + (size_t)brow * FPN + bn + bcol + 4);
    }
    __syncthreads();

    int p = 0;
    for (int k0 = 0; k0 < FPK; k0 += GBK) {
        const bool has_next = (k0 + GBK) < FPK;
        float4 a0g, a1g, b0g, b1g;
        if (has_next) {
            const float* arp = A + (size_t)(bm + arow) * FPK + k0 + GBK + ak;
            a0g = *(const float4*)arp;
            a1g = *(const float4*)(arp + 4);
            b0g = *(const float4*)(B + (size_t)(k0 + GBK + brow) * FPN + bn + bcol);
            b1g = *(const float4*)(B + (size_t)(k0 + GBK + brow) * FPN + bn + bcol + 4);
        }

        const float* Asp = As[p];
        const float* Bsp = Bs[p];
#pragma unroll
        for (int kk = 0; kk < GBK; kk++) {
            float4 a0 = *(const float4*)&Asp[kk * GBM + ty * 4];        // bcast
            float4 a1 = *(const float4*)&Asp[kk * GBM + 64 + ty * 4];   // bcast
            ulonglong2 b0 = *(const ulonglong2*)&Bsp[kk * 128 + tx * 4];      // CF
            ulonglong2 b1 = *(const ulonglong2*)&Bsp[kk * 128 + 64 + tx * 4]; // CF
            ull b2[4] = {b0.x, b0.y, b1.x, b1.y};
            ull aa[8] = {pk2(a0.x, a0.x), pk2(a0.y, a0.y), pk2(a0.z, a0.z), pk2(a0.w, a0.w),
                         pk2(a1.x, a1.x), pk2(a1.y, a1.y), pk2(a1.z, a1.z), pk2(a1.w, a1.w)};
#pragma unroll
            for (int i = 0; i < 8; i++)
#pragma unroll
                for (int j = 0; j < 4; j++)
                    acc2[i][j] = fma2(aa[i], b2[j], acc2[i][j]);
        }

        if (has_next) {
            const int q = p ^ 1;
            As[q][(ak + 0) * GBM + arow] = a0g.x;
            As[q][(ak + 1) * GBM + arow] = a0g.y;
            As[q][(ak + 2) * GBM + arow] = a0g.z;
            As[q][(ak + 3) * GBM + arow] = a0g.w;
            As[q][(ak + 4) * GBM + arow] = a1g.x;
            As[q][(ak + 5) * GBM + arow] = a1g.y;
            As[q][(ak + 6) * GBM + arow] = a1g.z;
            As[q][(ak + 7) * GBM + arow] = a1g.w;
            *(float4*)&Bs[q][brow * 128 + bcol] = b0g;
            *(float4*)&Bs[q][brow * 128 + bcol + 4] = b1g;
            __syncthreads();
            p = q;
        }
    }

#pragma unroll
    for (int i = 0; i < 8; i++) {
        const int row = bm + ((i < 4) ? (ty * 4 + i) : (64 + ty * 4 + i - 4));
        float vlo[4], vhi[4];
        {
            float2 v0 = upk2(acc2[i][0]);
            float2 v1 = upk2(acc2[i][1]);
            vlo[0] = v0.x; vlo[1] = v0.y; vlo[2] = v1.x; vlo[3] = v1.y;
            float2 v2 = upk2(acc2[i][2]);
            float2 v3 = upk2(acc2[i][3]);
            vhi[0] = v2.x; vhi[1] = v2.y; vhi[2] = v3.x; vhi[3] = v3.y;
        }
#pragma unroll
        for (int j = 0; j < 4; j++) {
            const int clo = bn + tx * 4 + j;
            const int chi = bn + 64 + tx * 4 + j;
            float zl = vlo[j], zh = vhi[j];
            if (w == 0)      { zl *= qscale; zh *= qscale; }
            else if (w == 3) {
                zl = 1.f / (1.f + __expf(-(zl + bg[clo])));
                zh = 1.f / (1.f + __expf(-(zh + bg[chi])));
            }
            vlo[j] = zl; vhi[j] = zh;
        }
        *(float4*)(C + (size_t)row * FPN + bn + tx * 4) =
            make_float4(vlo[0], vlo[1], vlo[2], vlo[3]);
        *(float4*)(C + (size_t)row * FPN + bn + 64 + tx * 4) =
            make_float4(vhi[0], vhi[1], vhi[2], vhi[3]);
    }
}

// ---------------------------------------------------------------------------
// fp32 SGEMM v6 (94.7us config) for the output projection (N=128, K=256).
// ---------------------------------------------------------------------------
__global__ __launch_bounds__(256, 2)
void sgemm6(const float* __restrict__ A, const float* __restrict__ B,
            float* __restrict__ C, int M, int N, int K,
            const float* __restrict__ evec)
{
    __shared__ float As[2][GBK * GBM];
    __shared__ float Bs[2][GBK * GBM];

    const int t  = threadIdx.x;
    const int bm = blockIdx.y * GBM;
    const int bn = blockIdx.x * 128;

    const int arow = t >> 1;
    const int ak   = (t & 1) * 8;
    const int brow = t >> 4;
    const int bcol = (t & 15) * 8;

    const int tx = t & 15;
    const int ty = t >> 4;

    ull acc2[8][4];
#pragma unroll
    for (int i = 0; i < 8; i++)
#pragma unroll
        for (int j = 0; j < 4; j++) acc2[i][j] = 0ULL;

    {
        const float* arp = A + (size_t)(bm + arow) * K + ak;
        float4 a0 = *(const float4*)arp;
        float4 a1 = *(const float4*)(arp + 4);
        As[0][(ak + 0) * GBM + arow] = a0.x;
        As[0][(ak + 1) * GBM + arow] = a0.y;
        As[0][(ak + 2) * GBM + arow] = a0.z;
        As[0][(ak + 3) * GBM + arow] = a0.w;
        As[0][(ak + 4) * GBM + arow] = a1.x;
        As[0][(ak + 5) * GBM + arow] = a1.y;
        As[0][(ak + 6) * GBM + arow] = a1.z;
        As[0][(ak + 7) * GBM + arow] = a1.w;
        *(float4*)&Bs[0][brow * 128 + bcol] =
            *(const float4*)(B + (size_t)brow * N + bn + bcol);
        *(float4*)&Bs[0][brow * 128 + bcol + 4] =
            *(const float4*)(B + (size_t)brow * N + bn + bcol + 4);
    }
    __syncthreads();

    int p = 0;
    for (int k0 = 0; k0 < K; k0 += GBK) {
        const bool has_next = (k0 + GBK) < K;
        float4 a0g, a1g, b0g, b1g;
        if (has_next) {
            const float* arp = A + (size_t)(bm + arow) * K + k0 + GBK + ak;
            a0g = *(const float4*)arp;
            a1g = *(const float4*)(arp + 4);
            b0g = *(const float4*)(B + (size_t)(k0 + GBK + brow) * N + bn + bcol);
            b1g = *(const float4*)(B + (size_t)(k0 + GBK + brow) * N + bn + bcol + 4);
        }

        const float* Asp = As[p];
        const float* Bsp = Bs[p];
#pragma unroll
        for (int kk = 0; kk < GBK; kk++) {
            float4 a0 = *(const float4*)&Asp[kk * GBM + ty * 4];
            float4 a1 = *(const float4*)&Asp[kk * GBM + 64 + ty * 4];
            ulonglong2 b0 = *(const ulonglong2*)&Bsp[kk * 128 + tx * 4];
            ulonglong2 b1 = *(const ulonglong2*)&Bsp[kk * 128 + 64 + tx * 4];
            ull b2[4] = {b0.x, b0.y, b1.x, b1.y};
            ull aa[8] = {pk2(a0.x, a0.x), pk2(a0.y, a0.y), pk2(a0.z, a0.z), pk2(a0.w, a0.w),
                         pk2(a1.x, a1.x), pk2(a1.y, a1.y), pk2(a1.z, a1.z), pk2(a1.w, a1.w)};
#pragma unroll
            for (int i = 0; i < 8; i++)
#pragma unroll
                for (int j = 0; j < 4; j++)
                    acc2[i][j] = fma2(aa[i], b2[j], acc2[i][j]);
        }

        if (has_next) {
            const int q = p ^ 1;
            As[q][(ak + 0) * GBM + arow] = a0g.x;
            As[q][(ak + 1) * GBM + arow] = a0g.y;
            As[q][(ak + 2) * GBM + arow] = a0g.z;
            As[q][(ak + 3) * GBM + arow] = a0g.w;
            As[q][(ak + 4) * GBM + arow] = a1g.x;
            As[q][(ak + 5) * GBM + arow] = a1g.y;
            As[q][(ak + 6) * GBM + arow] = a1g.z;
            As[q][(ak + 7) * GBM + arow] = a1g.w;
            *(float4*)&Bs[q][brow * 128 + bcol] = b0g;
            *(float4*)&Bs[q][brow * 128 + bcol + 4] = b1g;
            __syncthreads();
            p = q;
        }
    }

#pragma unroll
    for (int i = 0; i < 8; i++) {
        const int row = bm + ((i < 4) ? (ty * 4 + i) : (64 + ty * 4 + i - 4));
        float vlo[4], vhi[4];
        {
            float2 v0 = upk2(acc2[i][0]);
            float2 v1 = upk2(acc2[i][1]);
            vlo[0] = v0.x; vlo[1] = v0.y; vlo[2] = v1.x; vlo[3] = v1.y;
            float2 v2 = upk2(acc2[i][2]);
            float2 v3 = upk2(acc2[i][3]);
            vhi[0] = v2.x; vhi[1] = v2.y; vhi[2] = v3.x; vhi[3] = v3.y;
        }
#pragma unroll
        for (int j = 0; j < 4; j++) {
            vlo[j] += evec[bn + tx * 4 + j];
            vhi[j] += evec[bn + 64 + tx * 4 + j];
        }
        *(float4*)(C + (size_t)row * N + bn + tx * 4) =
            make_float4(vlo[0], vlo[1], vlo[2], vlo[3]);
        *(float4*)(C + (size_t)row * N + bn + 64 + tx * 4) =
            make_float4(vhi[0], vhi[1], vhi[2], vhi[3]);
    }
}

// ---------------------------------------------------------------------------
// Attention v8: attn5 structure with fp16 P and fp16 Q in smem + V staged
// over the dead K region -> 106KB smem -> 2 CTAs/SM (4 warps/SMSP).
// Block = (h, s, qh): 128 q x 256 k, 256 threads.
// smem bytes: Lh (fp16, stride 260) 66560 @0 | Ks fp32 32768 @66560 |
//   Qh fp16 8192 @99328 | addm 1024 @107520 | Vs fp32 32768 @66560 (phase 2)
// ---------------------------------------------------------------------------
#define LSTRH 260
#define AT_OFF_KS   66560
#define AT_OFF_QH   99328
#define AT_OFF_ADDM 107520
#define AT_OFF_VS   66560
#define ATTN_SMEM_BYTES 108544

__global__ __launch_bounds__(256, 2)
void attn8(const float* __restrict__ Q, const float* __restrict__ Km,
           const float* __restrict__ V, const float* __restrict__ G,
           const float* __restrict__ bias, const void* __restrict__ mask,
           float* __restrict__ O)
{
    extern __shared__ char smraw[];
    __half* Lh   = (__half*)smraw;
    float*  Ks   = (float*)(smraw + AT_OFF_KS);
    __half* Qh   = (__half*)(smraw + AT_OFF_QH);
    float*  addm = (float*)(smraw + AT_OFF_ADDM);
    float*  Vs   = (float*)(smraw + AT_OFF_VS);

    const int h  = blockIdx.x;
    const int s  = blockIdx.y;
    const int qh = blockIdx.z;
    const int t  = threadIdx.x;

    // ---- stage Q transposed fp16: Qh[c][q] ----
    {
        const int q = t >> 1, c0 = (t & 1) * 16;
        const float4* src = (const float4*)(Q + ((size_t)(s * S_DIM + qh * 128 + q)) * CQK + h * CH + c0);
#pragma unroll
        for (int j = 0; j < 4; j++) {
            float4 v = src[j];
            Qh[(c0 + 4 * j + 0) * 128 + q] = __float2half_rn(v.x);
            Qh[(c0 + 4 * j + 1) * 128 + q] = __float2half_rn(v.y);
            Qh[(c0 + 4 * j + 2) * 128 + q] = __float2half_rn(v.z);
            Qh[(c0 + 4 * j + 3) * 128 + q] = __float2half_rn(v.w);
        }
    }
    // ---- stage K transposed fp32: Ks[c][k], k = t ----
    {
        const int k = t;
        const float4* src = (const float4*)(Km + ((size_t)(s * S_DIM + k)) * CQK + h * CH);
#pragma unroll
        for (int j = 0; j < 8; j++) {
            float4 v = src[j];
            Ks[(4 * j + 0) * S_DIM + k] = v.x;
            Ks[(4 * j + 1) * S_DIM + k] = v.y;
            Ks[(4 * j + 2) * S_DIM + k] = v.z;
            Ks[(4 * j + 3) * S_DIM + k] = v.w;
        }
    }
    // ---- mask -> additive ----
    {
        const int idx = s * S_DIM + t;
        const int code = g_mask_code;
        bool mv;
        if (code == 2)      mv = ((const float*)mask)[idx] != 0.f;
        else if (code == 1) mv = ((const unsigned char*)mask)[idx] != 0;
        else                mv = ((const int*)mask)[idx] != 0;
        addm[t] = mv ? 0.f : -1e30f;
    }
    __syncthreads();

    // ---- pass 1 + fused shfl softmax; P stored fp16 ----
    const float* brow = bias + ((size_t)(h * S_DIM + qh * 128)) * S_DIM;
#pragma unroll
    for (int rep = 0; rep < 2; rep++) {
        const int tile = t + rep * 256;
        const int qi = tile >> 5, ki = tile & 31;   // qi warp-uniform
        const int q0 = qi * 8;
        const int kA = ki * 4, kB = 128 + ki * 4;

        ull acc2[8][4];
#pragma unroll
        for (int i = 0; i < 8; i++)
#pragma unroll
            for (int j = 0; j < 4; j++) acc2[i][j] = 0ULL;

#pragma unroll 2
        for (int c = 0; c < CH; c++) {
            // Q: 8 halves = 16B broadcast load, convert to 4 float2
            float4 qraw = *(const float4*)&Qh[c * 128 + q0];
            float2 f0 = __half22float2(*(__half2*)&qraw.x);
            float2 f1 = __half22float2(*(__half2*)&qraw.y);
            float2 f2 = __half22float2(*(__half2*)&qraw.z);
            float2 f3 = __half22float2(*(__half2*)&qraw.w);
            ulonglong2 k0v = *(const ulonglong2*)&Ks[c * S_DIM + kA];  // CF
            ulonglong2 k1v = *(const ulonglong2*)&Ks[c * S_DIM + kB];  // CF
            ull b2[4] = {k0v.x, k0v.y, k1v.x, k1v.y};
            ull aa[8] = {pk2(f0.x, f0.x), pk2(f0.y, f0.y), pk2(f1.x, f1.x), pk2(f1.y, f1.y),
                         pk2(f2.x, f2.x), pk2(f2.y, f2.y), pk2(f3.x, f3.x), pk2(f3.y, f3.y)};
#pragma unroll
            for (int i = 0; i < 8; i++)
#pragma unroll
                for (int j = 0; j < 4; j++)
                    acc2[i][j] = fma2(aa[i], b2[j], acc2[i][j]);
        }

        // unpack + bias + mask into v[8][8]
        float v[8][8];
        {
            float4 amA = *(const float4*)&addm[kA];
            float4 amB = *(const float4*)&addm[kB];
#pragma unroll
            for (int i = 0; i < 8; i++) {
                const int q = q0 + i;
                float4 bbA = *(const float4*)(brow + (size_t)q * S_DIM + kA);
                float4 bbB = *(const float4*)(brow + (size_t)q * S_DIM + kB);
                float2 d0 = upk2(acc2[i][0]);
                float2 d1 = upk2(acc2[i][1]);
                float2 d2 = upk2(acc2[i][2]);
                float2 d3 = upk2(acc2[i][3]);
                v[i][0] = d0.x + bbA.x + amA.x;
                v[i][1] = d0.y + bbA.y + amA.y;
                v[i][2] = d1.x + bbA.z + amA.z;
                v[i][3] = d1.y + bbA.w + amA.w;
                v[i][4] = d2.x + bbB.x + amB.x;
                v[i][5] = d2.y + bbB.y + amB.y;
                v[i][6] = d3.x + bbB.z + amB.z;
                v[i][7] = d3.y + bbB.w + amB.w;
            }
        }

        // row max across warp (ILP-8 butterfly)
        float rm[8];
#pragma unroll
        for (int i = 0; i < 8; i++) {
            float m01 = fmaxf(fmaxf(v[i][0], v[i][1]), fmaxf(v[i][2], v[i][3]));
            float m23 = fmaxf(fmaxf(v[i][4], v[i][5]), fmaxf(v[i][6], v[i][7]));
            rm[i] = fmaxf(m01, m23);
        }
#pragma unroll
        for (int st = 16; st >= 1; st >>= 1)
#pragma unroll
            for (int i = 0; i < 8; i++)
                rm[i] = fmaxf(rm[i], __shfl_xor_sync(0xFFFFFFFFu, rm[i], st));

        // exp + row sum across warp
        float rs[8];
#pragma unroll
        for (int i = 0; i < 8; i++) {
            float s0 = 0.f;
#pragma unroll
            for (int j = 0; j < 8; j++) {
                v[i][j] = __expf(v[i][j] - rm[i]);
                s0 += v[i][j];
            }
            rs[i] = s0;
        }
#pragma unroll
        for (int st = 16; st >= 1; st >>= 1)
#pragma unroll
            for (int i = 0; i < 8; i++)
                rs[i] += __shfl_xor_sync(0xFFFFFFFFu, rs[i], st);

        // normalize + store P fp16 (two 8B stores per row)
#pragma unroll
        for (int i = 0; i < 8; i++) {
            const int q = q0 + i;
            const float riv = 1.f / rs[i];
            __half2 pA0 = __floats2half2_rn(v[i][0] * riv, v[i][1] * riv);
            __half2 pA1 = __floats2half2_rn(v[i][2] * riv, v[i][3] * riv);
            __half2 pB0 = __floats2half2_rn(v[i][4] * riv, v[i][5] * riv);
            __half2 pB1 = __floats2half2_rn(v[i][6] * riv, v[i][7] * riv);
            uint2 wa, wb;
            wa.x = *(unsigned*)&pA0; wa.y = *(unsigned*)&pA1;
            wb.x = *(unsigned*)&pB0; wb.y = *(unsigned*)&pB1;
            *(uint2*)&Lh[q * LSTRH + kA] = wa;
            *(uint2*)&Lh[q * LSTRH + kB] = wb;
        }
    }
    __syncthreads();

    // ---- stage V fp32 [k][c] over the dead Ks region ----
    {
        const float4* Vg4 = (const float4*)V;
        const size_t rowbase = ((size_t)s * S_DIM) * (CQK / 4) + h * (CH / 4);
#pragma unroll
        for (int f = t; f < S_DIM * (CH / 4); f += 256) {
            int k = f >> 3, c4 = f & 7;
            ((float4*)Vs)[k * 8 + c4] = Vg4[rowbase + (size_t)k * (CQK / 4) + c4];
        }
    }
    __syncthreads();

    // ---- pass 2: O = P.V, 4q x 4c per thread (P fp16, pre-normalized) ----
    {
        const int qi = t >> 3, ci = t & 7;
        const int q0 = qi * 4, c0 = ci * 4;
        ull acc2[4][2];
#pragma unroll
        for (int i = 0; i < 4; i++) { acc2[i][0] = 0ULL; acc2[i][1] = 0ULL; }

#pragma unroll 2
        for (int k0 = 0; k0 < S_DIM; k0 += 4) {
            ulonglong2 v0 = *(const ulonglong2*)&Vs[(k0 + 0) * CH + c0];
            ulonglong2 v1 = *(const ulonglong2*)&Vs[(k0 + 1) * CH + c0];
            ulonglong2 v2 = *(const ulonglong2*)&Vs[(k0 + 2) * CH + c0];
            ulonglong2 v3 = *(const ulonglong2*)&Vs[(k0 + 3) * CH + c0];
#pragma unroll
            for (int i = 0; i < 4; i++) {
                uint2 w = *(const uint2*)&Lh[(q0 + i) * LSTRH + k0];
                float2 p01 = __half22float2(*(__half2*)&w.x);
                float2 p23 = __half22float2(*(__half2*)&w.y);
                ull a0 = pk2(p01.x, p01.x);
                ull a1 = pk2(p01.y, p01.y);
                ull a2 = pk2(p23.x, p23.x);
                ull a3 = pk2(p23.y, p23.y);
                acc2[i][0] = fma2(a0, v0.x, acc2[i][0]);
                acc2[i][1] = fma2(a0, v0.y, acc2[i][1]);
                acc2[i][0] = fma2(a1, v1.x, acc2[i][0]);
                acc2[i][1] = fma2(a1, v1.y, acc2[i][1]);
                acc2[i][0] = fma2(a2, v2.x, acc2[i][0]);
                acc2[i][1] = fma2(a2, v2.y, acc2[i][1]);
                acc2[i][0] = fma2(a3, v3.x, acc2[i][0]);
                acc2[i][1] = fma2(a3, v3.y, acc2[i][1]);
            }
        }
#pragma unroll
        for (int i = 0; i < 4; i++) {
            const int q = q0 + i;
            const size_t row = (size_t)(s * S_DIM + qh * 128 + q);
            float4 gv = *(const float4*)(G + row * CQK + h * CH + c0);
            float2 x0 = upk2(acc2[i][0]);
            float2 x1 = upk2(acc2[i][1]);
            float4 ov;
            ov.x = x0.x * gv.x;
            ov.y = x0.y * gv.y;
            ov.z = x1.x * gv.z;
            ov.w = x1.y * gv.w;
            *(float4*)(O + row * CQK + h * CH + c0) = ov;
        }
    }
}

// ---------------------------------------------------------------------------
// Launch
// ---------------------------------------------------------------------------
extern "C" void kernel_launch(void* const* d_in, const int* in_sizes, int n_in,
                              void* d_out, int out_size)
{
    const float* x    = (const float*)d_in[0];
    const float* bias = (const float*)d_in[1];
    const void*  mask = d_in[2];
    const float* Wq   = (const float*)d_in[3];
    const float* Wk   = (const float*)d_in[4];
    const float* Wv   = (const float*)d_in[5];
    const float* Wo   = (const float*)d_in[6];
    const float* bo   = (const float*)d_in[7];
    const float* Wg   = (const float*)d_in[8];
    const float* bg   = (const float*)d_in[9];
    float* out = (float*)d_out;

    void *pQ, *pK, *pV, *pG, *pO;
    cudaGetSymbolAddress(&pQ, g_Q);
    cudaGetSymbolAddress(&pK, g_K);
    cudaGetSymbolAddress(&pV, g_V);
    cudaGetSymbolAddress(&pG, g_G);
    cudaGetSymbolAddress(&pO, g_O);
    float* Qb = (float*)pQ; float* Kb = (float*)pK; float* Vb = (float*)pV;
    float* Gb = (float*)pG; float* Ob = (float*)pO;

    const float qscale = 0.17677669529663687f;   // 1/sqrt(32)

    fused_proj<<<dim3(8, NROWS / GBM), 256>>>(x, Wq, Wk, Wv, Wg,
                                              Qb, Kb, Vb, Gb, bg, qscale);

    detect_mask_kernel<<<1, 256>>>((const unsigned char*)mask, S_DIM * S_DIM);

    cudaFuncSetAttribute(attn8, cudaFuncAttributeMaxDynamicSharedMemorySize, ATTN_SMEM_BYTES);
    attn8<<<dim3(NH, S_DIM, 2), 256, ATTN_SMEM_BYTES>>>(Qb, Kb, Vb, Gb, bias, mask, Ob);

    sgemm6<<<dim3(1, NROWS / GBM), 256>>>(Ob, Wo, out, NROWS, CIN, CQK, bo);
}

// round 14
// speedup vs baseline: 1.3350x; 1.1475x over previous
#include <cuda_runtime.h>
#include <cuda_fp16.h>
#include <cstdint>
#include <math.h>

// Problem constants
#define S_DIM 256
#define CH    32          // head dim
#define NH    8           // heads
#define CIN   128         // input channels
#define CQK   256         // NH*CH
#define NROWS (S_DIM * S_DIM)

typedef unsigned long long ull;

// ---------------------------------------------------------------------------
// Packed f32x2 helpers (sm_103a FFMA2 path — PTX-only)
// ---------------------------------------------------------------------------
__device__ __forceinline__ ull pk2(float lo, float hi) {
    ull r; asm("mov.b64 %0, {%1, %2};" : "=l"(r) : "f"(lo), "f"(hi)); return r;
}
__device__ __forceinline__ float2 upk2(ull v) {
    float lo, hi; asm("mov.b64 {%0, %1}, %2;" : "=f"(lo), "=f"(hi) : "l"(v));
    return make_float2(lo, hi);
}
__device__ __forceinline__ ull fma2(ull a, ull b, ull c) {
    ull d; asm("fma.rn.f32x2 %0, %1, %2, %3;" : "=l"(d) : "l"(a), "l"(b), "l"(c)); return d;
}

// ---------------------------------------------------------------------------
// Scratch (Q/K/V/G fp16; O fp32; bias fp16 copy)
// ---------------------------------------------------------------------------
__device__ __half g_QH[(size_t)NROWS * CQK];
__device__ __half g_KH[(size_t)NROWS * CQK];
__device__ __half g_VH[(size_t)NROWS * CQK];
__device__ __half g_GH[(size_t)NROWS * CQK];
__device__ float  g_O[(size_t)NROWS * CQK];
__device__ __half g_biasH[(size_t)NH * S_DIM * S_DIM];
__device__ int    g_f_float, g_f_u8;

// ---------------------------------------------------------------------------
// Mask dtype detection (parallel, flag-based)
// ---------------------------------------------------------------------------
__global__ void init_flags_kernel() { g_f_float = 0; g_f_u8 = 0; }

__global__ void detect_mask_kernel(const unsigned char* __restrict__ m, int nbytes)
{
    int lf = 0, lu = 0;
    for (int i = blockIdx.x * 256 + threadIdx.x; i < nbytes; i += gridDim.x * 256) {
        unsigned char v = m[i];
        if (v >= 2) lf = 1;
        if ((i & 3) && v) lu = 1;
    }
    if (lf) atomicOr(&g_f_float, 1);
    if (lu) atomicOr(&g_f_u8, 1);
}

// ---------------------------------------------------------------------------
// bias fp32 -> fp16 convert (one shot per launch; 2MB -> 1MB)
// ---------------------------------------------------------------------------
__global__ void conv_bias_kernel(const float* __restrict__ b, __half* __restrict__ bh)
{
    const int i = (blockIdx.x * 256 + threadIdx.x) * 4;
    float4 v = *(const float4*)(b + i);
    __half2 h0 = __floats2half2_rn(v.x, v.y);
    __half2 h1 = __floats2half2_rn(v.z, v.w);
    uint2 w; w.x = *(unsigned*)&h0; w.y = *(unsigned*)&h1;
    *(uint2*)(bh + i) = w;
}

// ---------------------------------------------------------------------------
// Fused Q/K/V/G projection GEMM -> fp16 outputs. ONE launch, grid (8, 512).
// blockIdx.x: bit0 = n-half, bits1-2 = weight. 128x128 tile, BK=16, FFMA2.
// ---------------------------------------------------------------------------
#define GBM 128
#define GBK 16
#define FPN 256
#define FPK 128

__global__ __launch_bounds__(256, 2)
void fused_proj(const float* __restrict__ A,
                const float* __restrict__ Wq, const float* __restrict__ Wk,
                const float* __restrict__ Wv, const float* __restrict__ Wg,
                __half* __restrict__ Qb, __half* __restrict__ Kb,
                __half* __restrict__ Vb, __half* __restrict__ Gb,
                const float* __restrict__ bg, float qscale)
{
    __shared__ float As[2][GBK * GBM];
    __shared__ float Bs[2][GBK * GBM];

    const int t  = threadIdx.x;
    const int w  = blockIdx.x >> 1;
    const int bn = (blockIdx.x & 1) * 128;
    const int bm = blockIdx.y * GBM;

    const float* B; __half* C;
    if      (w == 0) { B = Wq; C = Qb; }
    else if (w == 1) { B = Wk; C = Kb; }
    else if (w == 2) { B = Wv; C = Vb; }
    else             { B = Wg; C = Gb; }

    const int arow = t >> 1;
    const int ak   = (t & 1) * 8;
    const int brow = t >> 4;
    const int bcol = (t & 15) * 8;

    const int tx = t & 15;
    const int ty = t >> 4;

    ull acc2[8][4];
#pragma unroll
    for (int i = 0; i < 8; i++)
#pragma unroll
        for (int j = 0; j < 4; j++) acc2[i][j] = 0ULL;

    {
        const float* arp = A + (size_t)(bm + arow) * FPK + ak;
        float4 a0 = *(const float4*)arp;
        float4 a1 = *(const float4*)(arp + 4);
        As[0][(ak + 0) * GBM + arow] = a0.x;
        As[0][(ak + 1) * GBM + arow] = a0.y;
        As[0][(ak + 2) * GBM + arow] = a0.z;
        As[0][(ak + 3) * GBM + arow] = a0.w;
        As[0][(ak + 4) * GBM + arow] = a1.x;
        As[0][(ak + 5) * GBM + arow] = a1.y;
        As[0][(ak + 6) * GBM + arow] = a1.z;
        As[0][(ak + 7) * GBM + arow] = a1.w;
        *(float4*)&Bs[0][brow * 128 + bcol] =
            *(const float4*)(B + (size_t)brow * FPN + bn + bcol);
        *(float4*)&Bs[0][brow * 128 + bcol + 4] =
            *(const float4*)(B + (size_t)brow * FPN + bn + bcol + 4);
    }
    __syncthreads();

    int p = 0;
    for (int k0 = 0; k0 < FPK; k0 += GBK) {
        const bool has_next = (k0 + GBK) < FPK;
        float4 a0g, a1g, b0g, b1g;
        if (has_next) {
            const float* arp = A + (size_t)(bm + arow) * FPK + k0 + GBK + ak;
            a0g = *(const float4*)arp;
            a1g = *(const float4*)(arp + 4);
            b0g = *(const float4*)(B + (size_t)(k0 + GBK + brow) * FPN + bn + bcol);
            b1g = *(const float4*)(B + (size_t)(k0 + GBK + brow) * FPN + bn + bcol + 4);
        }

        const float* Asp = As[p];
        const float* Bsp = Bs[p];
#pragma unroll
        for (int kk = 0; kk < GBK; kk++) {
            float4 a0 = *(const float4*)&Asp[kk * GBM + ty * 4];
            float4 a1 = *(const float4*)&Asp[kk * GBM + 64 + ty * 4];
            ulonglong2 b0 = *(const ulonglong2*)&Bsp[kk * 128 + tx * 4];
            ulonglong2 b1 = *(const ulonglong2*)&Bsp[kk * 128 + 64 + tx * 4];
            ull b2[4] = {b0.x, b0.y, b1.x, b1.y};
            ull aa[8] = {pk2(a0.x, a0.x), pk2(a0.y, a0.y), pk2(a0.z, a0.z), pk2(a0.w, a0.w),
                         pk2(a1.x, a1.x), pk2(a1.y, a1.y), pk2(a1.z, a1.z), pk2(a1.w, a1.w)};
#pragma unroll
            for (int i = 0; i < 8; i++)
#pragma unroll
                for (int j = 0; j < 4; j++)
                    acc2[i][j] = fma2(aa[i], b2[j], acc2[i][j]);
        }

        if (has_next) {
            const int q = p ^ 1;
            As[q][(ak + 0) * GBM + arow] = a0g.x;
            As[q][(ak + 1) * GBM + arow] = a0g.y;
            As[q][(ak + 2) * GBM + arow] = a0g.z;
            As[q][(ak + 3) * GBM + arow] = a0g.w;
            As[q][(ak + 4) * GBM + arow] = a1g.x;
            As[q][(ak + 5) * GBM + arow] = a1g.y;
            As[q][(ak + 6) * GBM + arow] = a1g.z;
            As[q][(ak + 7) * GBM + arow] = a1g.w;
            *(float4*)&Bs[q][brow * 128 + bcol] = b0g;
            *(float4*)&Bs[q][brow * 128 + bcol + 4] = b1g;
            __syncthreads();
            p = q;
        }
    }

#pragma unroll
    for (int i = 0; i < 8; i++) {
        const int row = bm + ((i < 4) ? (ty * 4 + i) : (64 + ty * 4 + i - 4));
        float vlo[4], vhi[4];
        {
            float2 v0 = upk2(acc2[i][0]);
            float2 v1 = upk2(acc2[i][1]);
            vlo[0] = v0.x; vlo[1] = v0.y; vlo[2] = v1.x; vlo[3] = v1.y;
            float2 v2 = upk2(acc2[i][2]);
            float2 v3 = upk2(acc2[i][3]);
            vhi[0] = v2.x; vhi[1] = v2.y; vhi[2] = v3.x; vhi[3] = v3.y;
        }
#pragma unroll
        for (int j = 0; j < 4; j++) {
            const int clo = bn + tx * 4 + j;
            const int chi = bn + 64 + tx * 4 + j;
            float zl = vlo[j], zh = vhi[j];
            if (w == 0)      { zl *= qscale; zh *= qscale; }
            else if (w == 3) {
                zl = 1.f / (1.f + __expf(-(zl + bg[clo])));
                zh = 1.f / (1.f + __expf(-(zh + bg[chi])));
            }
            vlo[j] = zl; vhi[j] = zh;
        }
        {
            __half2 h0 = __floats2half2_rn(vlo[0], vlo[1]);
            __half2 h1 = __floats2half2_rn(vlo[2], vlo[3]);
            uint2 wv; wv.x = *(unsigned*)&h0; wv.y = *(unsigned*)&h1;
            *(uint2*)(C + (size_t)row * FPN + bn + tx * 4) = wv;
            __half2 h2 = __floats2half2_rn(vhi[0], vhi[1]);
            __half2 h3 = __floats2half2_rn(vhi[2], vhi[3]);
            uint2 wh; wh.x = *(unsigned*)&h2; wh.y = *(unsigned*)&h3;
            *(uint2*)(C + (size_t)row * FPN + bn + 64 + tx * 4) = wh;
        }
    }
}

// ---------------------------------------------------------------------------
// fp32 SGEMM v6 for output projection (N=128, K=256) — unchanged.
// ---------------------------------------------------------------------------
__global__ __launch_bounds__(256, 2)
void sgemm6(const float* __restrict__ A, const float* __restrict__ B,
            float* __restrict__ C, int M, int N, int K,
            const float* __restrict__ evec)
{
    __shared__ float As[2][GBK * GBM];
    __shared__ float Bs[2][GBK * GBM];

    const int t  = threadIdx.x;
    const int bm = blockIdx.y * GBM;
    const int bn = blockIdx.x * 128;

    const int arow = t >> 1;
    const int ak   = (t & 1) * 8;
    const int brow = t >> 4;
    const int bcol = (t & 15) * 8;

    const int tx = t & 15;
    const int ty = t >> 4;

    ull acc2[8][4];
#pragma unroll
    for (int i = 0; i < 8; i++)
#pragma unroll
        for (int j = 0; j < 4; j++) acc2[i][j] = 0ULL;

    {
        const float* arp = A + (size_t)(bm + arow) * K + ak;
        float4 a0 = *(const float4*)arp;
        float4 a1 = *(const float4*)(arp + 4);
        As[0][(ak + 0) * GBM + arow] = a0.x;
        As[0][(ak + 1) * GBM + arow] = a0.y;
        As[0][(ak + 2) * GBM + arow] = a0.z;
        As[0][(ak + 3) * GBM + arow] = a0.w;
        As[0][(ak + 4) * GBM + arow] = a1.x;
        As[0][(ak + 5) * GBM + arow] = a1.y;
        As[0][(ak + 6) * GBM + arow] = a1.z;
        As[0][(ak + 7) * GBM + arow] = a1.w;
        *(float4*)&Bs[0][brow * 128 + bcol] =
            *(const float4*)(B + (size_t)brow * N + bn + bcol);
        *(float4*)&Bs[0][brow * 128 + bcol + 4] =
            *(const float4*)(B + (size_t)brow * N + bn + bcol + 4);
    }
    __syncthreads();

    int p = 0;
    for (int k0 = 0; k0 < K; k0 += GBK) {
        const bool has_next = (k0 + GBK) < K;
        float4 a0g, a1g, b0g, b1g;
        if (has_next) {
            const float* arp = A + (size_t)(bm + arow) * K + k0 + GBK + ak;
            a0g = *(const float4*)arp;
            a1g = *(const float4*)(arp + 4);
            b0g = *(const float4*)(B + (size_t)(k0 + GBK + brow) * N + bn + bcol);
            b1g = *(const float4*)(B + (size_t)(k0 + GBK + brow) * N + bn + bcol + 4);
        }

        const float* Asp = As[p];
        const float* Bsp = Bs[p];
#pragma unroll
        for (int kk = 0; kk < GBK; kk++) {
            float4 a0 = *(const float4*)&Asp[kk * GBM + ty * 4];
            float4 a1 = *(const float4*)&Asp[kk * GBM + 64 + ty * 4];
            ulonglong2 b0 = *(const ulonglong2*)&Bsp[kk * 128 + tx * 4];
            ulonglong2 b1 = *(const ulonglong2*)&Bsp[kk * 128 + 64 + tx * 4];
            ull b2[4] = {b0.x, b0.y, b1.x, b1.y};
            ull aa[8] = {pk2(a0.x, a0.x), pk2(a0.y, a0.y), pk2(a0.z, a0.z), pk2(a0.w, a0.w),
                         pk2(a1.x, a1.x), pk2(a1.y, a1.y), pk2(a1.z, a1.z), pk2(a1.w, a1.w)};
#pragma unroll
            for (int i = 0; i < 8; i++)
#pragma unroll
                for (int j = 0; j < 4; j++)
                    acc2[i][j] = fma2(aa[i], b2[j], acc2[i][j]);
        }

        if (has_next) {
            const int q = p ^ 1;
            As[q][(ak + 0) * GBM + arow] = a0g.x;
            As[q][(ak + 1) * GBM + arow] = a0g.y;
            As[q][(ak + 2) * GBM + arow] = a0g.z;
            As[q][(ak + 3) * GBM + arow] = a0g.w;
            As[q][(ak + 4) * GBM + arow] = a1g.x;
            As[q][(ak + 5) * GBM + arow] = a1g.y;
            As[q][(ak + 6) * GBM + arow] = a1g.z;
            As[q][(ak + 7) * GBM + arow] = a1g.w;
            *(float4*)&Bs[q][brow * 128 + bcol] = b0g;
            *(float4*)&Bs[q][brow * 128 + bcol + 4] = b1g;
            __syncthreads();
            p = q;
        }
    }

#pragma unroll
    for (int i = 0; i < 8; i++) {
        const int row = bm + ((i < 4) ? (ty * 4 + i) : (64 + ty * 4 + i - 4));
        float vlo[4], vhi[4];
        {
            float2 v0 = upk2(acc2[i][0]);
            float2 v1 = upk2(acc2[i][1]);
            vlo[0] = v0.x; vlo[1] = v0.y; vlo[2] = v1.x; vlo[3] = v1.y;
            float2 v2 = upk2(acc2[i][2]);
            float2 v3 = upk2(acc2[i][3]);
            vhi[0] = v2.x; vhi[1] = v2.y; vhi[2] = v3.x; vhi[3] = v3.y;
        }
#pragma unroll
        for (int j = 0; j < 4; j++) {
            vlo[j] += evec[bn + tx * 4 + j];
            vhi[j] += evec[bn + 64 + tx * 4 + j];
        }
        *(float4*)(C + (size_t)row * N + bn + tx * 4) =
            make_float4(vlo[0], vlo[1], vlo[2], vlo[3]);
        *(float4*)(C + (size_t)row * N + bn + 64 + tx * 4) =
            make_float4(vhi[0], vhi[1], vhi[2], vhi[3]);
    }
}

// ---------------------------------------------------------------------------
// Attention v9: all-fp16 inputs (Q/K/V/G/bias gmem), fp32 arithmetic.
// Same structure as attn8: 128 q x 256 k, 256 threads, 2 CTAs/SM,
// fused shfl softmax, fp16 P, V staged over dead K region.
// ---------------------------------------------------------------------------
#define LSTRH 260
#define AT_OFF_KS   66560
#define AT_OFF_QH   99328
#define AT_OFF_ADDM 107520
#define AT_OFF_VS   66560
#define ATTN_SMEM_BYTES 108544

__global__ __launch_bounds__(256, 2)
void attn9(const __half* __restrict__ Q, const __half* __restrict__ Km,
           const __half* __restrict__ V, const __half* __restrict__ G,
           const __half* __restrict__ biasH, const void* __restrict__ mask,
           float* __restrict__ O)
{
    extern __shared__ char smraw[];
    __half* Lh   = (__half*)smraw;
    float*  Ks   = (float*)(smraw + AT_OFF_KS);
    __half* Qh   = (__half*)(smraw + AT_OFF_QH);
    float*  addm = (float*)(smraw + AT_OFF_ADDM);
    float*  Vs   = (float*)(smraw + AT_OFF_VS);

    const int h  = blockIdx.x;
    const int s  = blockIdx.y;
    const int qh = blockIdx.z;
    const int t  = threadIdx.x;

    // ---- stage Q fp16 transposed (direct copy): Qh[c][q] ----
    {
        const int q = t >> 1, c0 = (t & 1) * 16;
        const uint4* src = (const uint4*)(Q + ((size_t)(s * S_DIM + qh * 128 + q)) * CQK + h * CH + c0);
#pragma unroll
        for (int j = 0; j < 2; j++) {
            uint4 w = src[j];
            const unsigned ws[4] = {w.x, w.y, w.z, w.w};
#pragma unroll
            for (int m = 0; m < 4; m++) {
                __half2 hp = *(const __half2*)&ws[m];
                const int c = c0 + j * 8 + m * 2;
                Qh[(c + 0) * 128 + q] = __low2half(hp);
                Qh[(c + 1) * 128 + q] = __high2half(hp);
            }
        }
    }
    // ---- stage K fp16 -> fp32 transposed: Ks[c][k], k = t ----
    {
        const int k = t;
        const uint4* src = (const uint4*)(Km + ((size_t)(s * S_DIM + k)) * CQK + h * CH);
#pragma unroll
        for (int j = 0; j < 4; j++) {
            uint4 w = src[j];
            const unsigned ws[4] = {w.x, w.y, w.z, w.w};
#pragma unroll
            for (int m = 0; m < 4; m++) {
                float2 f = __half22float2(*(const __half2*)&ws[m]);
                const int c = j * 8 + m * 2;
                Ks[(c + 0) * S_DIM + k] = f.x;
                Ks[(c + 1) * S_DIM + k] = f.y;
            }
        }
    }
    // ---- mask -> additive ----
    {
        const int idx = s * S_DIM + t;
        const int code = g_f_float ? 2 : (g_f_u8 ? 1 : 0);
        bool mv;
        if (code == 2)      mv = ((const float*)mask)[idx] != 0.f;
        else if (code == 1) mv = ((const unsigned char*)mask)[idx] != 0;
        else                mv = ((const int*)mask)[idx] != 0;
        addm[t] = mv ? 0.f : -1e30f;
    }
    __syncthreads();

    // ---- pass 1 + fused shfl softmax; P stored fp16 ----
    const __half* brow = biasH + ((size_t)(h * S_DIM + qh * 128)) * S_DIM;
#pragma unroll
    for (int rep = 0; rep < 2; rep++) {
        const int tile = t + rep * 256;
        const int qi = tile >> 5, ki = tile & 31;   // qi warp-uniform
        const int q0 = qi * 8;
        const int kA = ki * 4, kB = 128 + ki * 4;

        ull acc2[8][4];
#pragma unroll
        for (int i = 0; i < 8; i++)
#pragma unroll
            for (int j = 0; j < 4; j++) acc2[i][j] = 0ULL;

#pragma unroll 2
        for (int c = 0; c < CH; c++) {
            float4 qraw = *(const float4*)&Qh[c * 128 + q0];   // 8 halves, bcast
            float2 f0 = __half22float2(*(__half2*)&qraw.x);
            float2 f1 = __half22float2(*(__half2*)&qraw.y);
            float2 f2 = __half22float2(*(__half2*)&qraw.z);
            float2 f3 = __half22float2(*(__half2*)&qraw.w);
            ulonglong2 k0v = *(const ulonglong2*)&Ks[c * S_DIM + kA];  // CF
            ulonglong2 k1v = *(const ulonglong2*)&Ks[c * S_DIM + kB];  // CF
            ull b2[4] = {k0v.x, k0v.y, k1v.x, k1v.y};
            ull aa[8] = {pk2(f0.x, f0.x), pk2(f0.y, f0.y), pk2(f1.x, f1.x), pk2(f1.y, f1.y),
                         pk2(f2.x, f2.x), pk2(f2.y, f2.y), pk2(f3.x, f3.x), pk2(f3.y, f3.y)};
#pragma unroll
            for (int i = 0; i < 8; i++)
#pragma unroll
                for (int j = 0; j < 4; j++)
                    acc2[i][j] = fma2(aa[i], b2[j], acc2[i][j]);
        }

        // unpack + bias(fp16) + mask into v[8][8]
        float v[8][8];
        {
            float4 amA = *(const float4*)&addm[kA];
            float4 amB = *(const float4*)&addm[kB];
#pragma unroll
            for (int i = 0; i < 8; i++) {
                const int q = q0 + i;
                uint2 ba = *(const uint2*)(brow + (size_t)q * S_DIM + kA);
                uint2 bb = *(const uint2*)(brow + (size_t)q * S_DIM + kB);
                float2 bA0 = __half22float2(*(__half2*)&ba.x);
                float2 bA1 = __half22float2(*(__half2*)&ba.y);
                float2 bB0 = __half22float2(*(__half2*)&bb.x);
                float2 bB1 = __half22float2(*(__half2*)&bb.y);
                float2 d0 = upk2(acc2[i][0]);
                float2 d1 = upk2(acc2[i][1]);
                float2 d2 = upk2(acc2[i][2]);
                float2 d3 = upk2(acc2[i][3]);
                v[i][0] = d0.x + bA0.x + amA.x;
                v[i][1] = d0.y + bA0.y + amA.y;
                v[i][2] = d1.x + bA1.x + amA.z;
                v[i][3] = d1.y + bA1.y + amA.w;
                v[i][4] = d2.x + bB0.x + amB.x;
                v[i][5] = d2.y + bB0.y + amB.y;
                v[i][6] = d3.x + bB1.x + amB.z;
                v[i][7] = d3.y + bB1.y + amB.w;
            }
        }

        // row max across warp (ILP-8 butterfly)
        float rm[8];
#pragma unroll
        for (int i = 0; i < 8; i++) {
            float m01 = fmaxf(fmaxf(v[i][0], v[i][1]), fmaxf(v[i][2], v[i][3]));
            float m23 = fmaxf(fmaxf(v[i][4], v[i][5]), fmaxf(v[i][6], v[i][7]));
            rm[i] = fmaxf(m01, m23);
        }
#pragma unroll
        for (int st = 16; st >= 1; st >>= 1)
#pragma unroll
            for (int i = 0; i < 8; i++)
                rm[i] = fmaxf(rm[i], __shfl_xor_sync(0xFFFFFFFFu, rm[i], st));

        // exp + row sum across warp
        float rs[8];
#pragma unroll
        for (int i = 0; i < 8; i++) {
            float s0 = 0.f;
#pragma unroll
            for (int j = 0; j < 8; j++) {
                v[i][j] = __expf(v[i][j] - rm[i]);
                s0 += v[i][j];
            }
            rs[i] = s0;
        }
#pragma unroll
        for (int st = 16; st >= 1; st >>= 1)
#pragma unroll
            for (int i = 0; i < 8; i++)
                rs[i] += __shfl_xor_sync(0xFFFFFFFFu, rs[i], st);

        // normalize + store P fp16
#pragma unroll
        for (int i = 0; i < 8; i++) {
            const int q = q0 + i;
            const float riv = 1.f / rs[i];
            __half2 pA0 = __floats2half2_rn(v[i][0] * riv, v[i][1] * riv);
            __half2 pA1 = __floats2half2_rn(v[i][2] * riv, v[i][3] * riv);
            __half2 pB0 = __floats2half2_rn(v[i][4] * riv, v[i][5] * riv);
            __half2 pB1 = __floats2half2_rn(v[i][6] * riv, v[i][7] * riv);
            uint2 wa, wb;
            wa.x = *(unsigned*)&pA0; wa.y = *(unsigned*)&pA1;
            wb.x = *(unsigned*)&pB0; wb.y = *(unsigned*)&pB1;
            *(uint2*)&Lh[q * LSTRH + kA] = wa;
            *(uint2*)&Lh[q * LSTRH + kB] = wb;
        }
    }
    __syncthreads();

    // ---- stage V fp16 -> fp32 [k][c] over the dead Ks region ----
    {
#pragma unroll
        for (int f = t; f < S_DIM * 4; f += 256) {
            const int k = f >> 2, c0 = (f & 3) * 8;
            uint4 w = *(const uint4*)(V + ((size_t)(s * S_DIM + k)) * CQK + h * CH + c0);
            float2 f0 = __half22float2(*(__half2*)&w.x);
            float2 f1 = __half22float2(*(__half2*)&w.y);
            float2 f2 = __half22float2(*(__half2*)&w.z);
            float2 f3 = __half22float2(*(__half2*)&w.w);
            *(float4*)&Vs[k * CH + c0]     = make_float4(f0.x, f0.y, f1.x, f1.y);
            *(float4*)&Vs[k * CH + c0 + 4] = make_float4(f2.x, f2.y, f3.x, f3.y);
        }
    }
    __syncthreads();

    // ---- pass 2: O = P.V, 4q x 4c per thread ----
    {
        const int qi = t >> 3, ci = t & 7;
        const int q0 = qi * 4, c0 = ci * 4;
        ull acc2[4][2];
#pragma unroll
        for (int i = 0; i < 4; i++) { acc2[i][0] = 0ULL; acc2[i][1] = 0ULL; }

#pragma unroll 2
        for (int k0 = 0; k0 < S_DIM; k0 += 4) {
            ulonglong2 v0 = *(const ulonglong2*)&Vs[(k0 + 0) * CH + c0];
            ulonglong2 v1 = *(const ulonglong2*)&Vs[(k0 + 1) * CH + c0];
            ulonglong2 v2 = *(const ulonglong2*)&Vs[(k0 + 2) * CH + c0];
            ulonglong2 v3 = *(const ulonglong2*)&Vs[(k0 + 3) * CH + c0];
#pragma unroll
            for (int i = 0; i < 4; i++) {
                uint2 w = *(const uint2*)&Lh[(q0 + i) * LSTRH + k0];
                float2 p01 = __half22float2(*(__half2*)&w.x);
                float2 p23 = __half22float2(*(__half2*)&w.y);
                ull a0 = pk2(p01.x, p01.x);
                ull a1 = pk2(p01.y, p01.y);
                ull a2 = pk2(p23.x, p23.x);
                ull a3 = pk2(p23.y, p23.y);
                acc2[i][0] = fma2(a0, v0.x, acc2[i][0]);
                acc2[i][1] = fma2(a0, v0.y, acc2[i][1]);
                acc2[i][0] = fma2(a1, v1.x, acc2[i][0]);
                acc2[i][1] = fma2(a1, v1.y, acc2[i][1]);
                acc2[i][0] = fma2(a2, v2.x, acc2[i][0]);
                acc2[i][1] = fma2(a2, v2.y, acc2[i][1]);
                acc2[i][0] = fma2(a3, v3.x, acc2[i][0]);
                acc2[i][1] = fma2(a3, v3.y, acc2[i][1]);
            }
        }
#pragma unroll
        for (int i = 0; i < 4; i++) {
            const int q = q0 + i;
            const size_t row = (size_t)(s * S_DIM + qh * 128 + q);
            uint2 gw = *(const uint2*)(G + row * CQK + h * CH + c0);
            float2 g01 = __half22float2(*(__half2*)&gw.x);
            float2 g23 = __half22float2(*(__half2*)&gw.y);
            float2 x0 = upk2(acc2[i][0]);
            float2 x1 = upk2(acc2[i][1]);
            float4 ov;
            ov.x = x0.x * g01.x;
            ov.y = x0.y * g01.y;
            ov.z = x1.x * g23.x;
            ov.w = x1.y * g23.y;
            *(float4*)(O + row * CQK + h * CH + c0) = ov;
        }
    }
}

// ---------------------------------------------------------------------------
// Launch
// ---------------------------------------------------------------------------
extern "C" void kernel_launch(void* const* d_in, const int* in_sizes, int n_in,
                              void* d_out, int out_size)
{
    const float* x    = (const float*)d_in[0];
    const float* bias = (const float*)d_in[1];
    const void*  mask = d_in[2];
    const float* Wq   = (const float*)d_in[3];
    const float* Wk   = (const float*)d_in[4];
    const float* Wv   = (const float*)d_in[5];
    const float* Wo   = (const float*)d_in[6];
    const float* bo   = (const float*)d_in[7];
    const float* Wg   = (const float*)d_in[8];
    const float* bg   = (const float*)d_in[9];
    float* out = (float*)d_out;

    void *pQ, *pK, *pV, *pG, *pO, *pB;
    cudaGetSymbolAddress(&pQ, g_QH);
    cudaGetSymbolAddress(&pK, g_KH);
    cudaGetSymbolAddress(&pV, g_VH);
    cudaGetSymbolAddress(&pG, g_GH);
    cudaGetSymbolAddress(&pO, g_O);
    cudaGetSymbolAddress(&pB, g_biasH);
    __half* Qb = (__half*)pQ; __half* Kb = (__half*)pK; __half* Vb = (__half*)pV;
    __half* Gb = (__half*)pG; float* Ob = (float*)pO; __half* biasH = (__half*)pB;

    const float qscale = 0.17677669529663687f;   // 1/sqrt(32)

    init_flags_kernel<<<1, 1>>>();
    detect_mask_kernel<<<64, 256>>>((const unsigned char*)mask, S_DIM * S_DIM);
    conv_bias_kernel<<<(NH * S_DIM * S_DIM / 4) / 256, 256>>>(bias, biasH);

    fused_proj<<<dim3(8, NROWS / GBM), 256>>>(x, Wq, Wk, Wv, Wg,
                                              Qb, Kb, Vb, Gb, bg, qscale);

    cudaFuncSetAttribute(attn9, cudaFuncAttributeMaxDynamicSharedMemorySize, ATTN_SMEM_BYTES);
    attn9<<<dim3(NH, S_DIM, 2), 256, ATTN_SMEM_BYTES>>>(Qb, Kb, Vb, Gb, biasH, mask, Ob);

    sgemm6<<<dim3(1, NROWS / GBM), 256>>>(Ob, Wo, out, NROWS, CIN, CQK, bo);
}

// round 15
// speedup vs baseline: 1.8408x; 1.3789x over previous
#include <cuda_runtime.h>
#include <cuda_fp16.h>
#include <cstdint>
#include <math.h>

// Problem constants
#define S_DIM 256
#define CH    32          // head dim
#define NH    8           // heads
#define CIN   128         // input channels
#define CQK   256         // NH*CH
#define NROWS (S_DIM * S_DIM)

typedef unsigned long long ull;
typedef unsigned int uint_t;

// ---------------------------------------------------------------------------
// Packed f32x2 helpers (sm_103a FFMA2 path — PTX-only)
// ---------------------------------------------------------------------------
__device__ __forceinline__ ull pk2(float lo, float hi) {
    ull r; asm("mov.b64 %0, {%1, %2};" : "=l"(r) : "f"(lo), "f"(hi)); return r;
}
__device__ __forceinline__ float2 upk2(ull v) {
    float lo, hi; asm("mov.b64 {%0, %1}, %2;" : "=f"(lo), "=f"(hi) : "l"(v));
    return make_float2(lo, hi);
}
__device__ __forceinline__ ull fma2(ull a, ull b, ull c) {
    ull d; asm("fma.rn.f32x2 %0, %1, %2, %3;" : "=l"(d) : "l"(a), "l"(b), "l"(c)); return d;
}

// mma.sync m16n8k16 f16*f16 + f32 (baseline PTX, no 'a' feature)
__device__ __forceinline__ void mma16816(float& c0, float& c1, float& c2, float& c3,
                                         uint_t a0, uint_t a1, uint_t a2, uint_t a3,
                                         uint_t b0, uint_t b1)
{
    asm volatile(
        "mma.sync.aligned.m16n8k16.row.col.f32.f16.f16.f32 "
        "{%0,%1,%2,%3}, {%4,%5,%6,%7}, {%8,%9}, {%0,%1,%2,%3};"
        : "+f"(c0), "+f"(c1), "+f"(c2), "+f"(c3)
        : "r"(a0), "r"(a1), "r"(a2), "r"(a3), "r"(b0), "r"(b1));
}

// ---------------------------------------------------------------------------
// Scratch (Q/K/V/G fp16; O fp32; bias fp16 copy)
// ---------------------------------------------------------------------------
__device__ __half g_QH[(size_t)NROWS * CQK];
__device__ __half g_KH[(size_t)NROWS * CQK];
__device__ __half g_VH[(size_t)NROWS * CQK];
__device__ __half g_GH[(size_t)NROWS * CQK];
__device__ float  g_O[(size_t)NROWS * CQK];
__device__ __half g_biasH[(size_t)NH * S_DIM * S_DIM];
__device__ int    g_f_float, g_f_u8;

// ---------------------------------------------------------------------------
// Mask dtype detection (parallel) + bias fp32->fp16 convert
// ---------------------------------------------------------------------------
__global__ void init_flags_kernel() { g_f_float = 0; g_f_u8 = 0; }

__global__ void detect_mask_kernel(const unsigned char* __restrict__ m, int nbytes)
{
    int lf = 0, lu = 0;
    for (int i = blockIdx.x * 256 + threadIdx.x; i < nbytes; i += gridDim.x * 256) {
        unsigned char v = m[i];
        if (v >= 2) lf = 1;
        if ((i & 3) && v) lu = 1;
    }
    if (lf) atomicOr(&g_f_float, 1);
    if (lu) atomicOr(&g_f_u8, 1);
}

__global__ void conv_bias_kernel(const float* __restrict__ b, __half* __restrict__ bh)
{
    const int i = (blockIdx.x * 256 + threadIdx.x) * 4;
    float4 v = *(const float4*)(b + i);
    __half2 h0 = __floats2half2_rn(v.x, v.y);
    __half2 h1 = __floats2half2_rn(v.z, v.w);
    uint2 w; w.x = *(unsigned*)&h0; w.y = *(unsigned*)&h1;
    *(uint2*)(bh + i) = w;
}

// ---------------------------------------------------------------------------
// Fused Q/K/V/G projection GEMM -> fp16 outputs (round-14 version, FFMA2).
// ---------------------------------------------------------------------------
#define GBM 128
#define GBK 16
#define FPN 256
#define FPK 128

__global__ __launch_bounds__(256, 2)
void fused_proj(const float* __restrict__ A,
                const float* __restrict__ Wq, const float* __restrict__ Wk,
                const float* __restrict__ Wv, const float* __restrict__ Wg,
                __half* __restrict__ Qb, __half* __restrict__ Kb,
                __half* __restrict__ Vb, __half* __restrict__ Gb,
                const float* __restrict__ bg, float qscale)
{
    __shared__ float As[2][GBK * GBM];
    __shared__ float Bs[2][GBK * GBM];

    const int t  = threadIdx.x;
    const int w  = blockIdx.x >> 1;
    const int bn = (blockIdx.x & 1) * 128;
    const int bm = blockIdx.y * GBM;

    const float* B; __half* C;
    if      (w == 0) { B = Wq; C = Qb; }
    else if (w == 1) { B = Wk; C = Kb; }
    else if (w == 2) { B = Wv; C = Vb; }
    else             { B = Wg; C = Gb; }

    const int arow = t >> 1;
    const int ak   = (t & 1) * 8;
    const int brow = t >> 4;
    const int bcol = (t & 15) * 8;

    const int tx = t & 15;
    const int ty = t >> 4;

    ull acc2[8][4];
#pragma unroll
    for (int i = 0; i < 8; i++)
#pragma unroll
        for (int j = 0; j < 4; j++) acc2[i][j] = 0ULL;

    {
        const float* arp = A + (size_t)(bm + arow) * FPK + ak;
        float4 a0 = *(const float4*)arp;
        float4 a1 = *(const float4*)(arp + 4);
        As[0][(ak + 0) * GBM + arow] = a0.x;
        As[0][(ak + 1) * GBM + arow] = a0.y;
        As[0][(ak + 2) * GBM + arow] = a0.z;
        As[0][(ak + 3) * GBM + arow] = a0.w;
        As[0][(ak + 4) * GBM + arow] = a1.x;
        As[0][(ak + 5) * GBM + arow] = a1.y;
        As[0][(ak + 6) * GBM + arow] = a1.z;
        As[0][(ak + 7) * GBM + arow] = a1.w;
        *(float4*)&Bs[0][brow * 128 + bcol] =
            *(const float4*)(B + (size_t)brow * FPN + bn + bcol);
        *(float4*)&Bs[0][brow * 128 + bcol + 4] =
            *(const float4*)(B + (size_t)brow * FPN + bn + bcol + 4);
    }
    __syncthreads();

    int p = 0;
    for (int k0 = 0; k0 < FPK; k0 += GBK) {
        const bool has_next = (k0 + GBK) < FPK;
        float4 a0g, a1g, b0g, b1g;
        if (has_next) {
            const float* arp = A + (size_t)(bm + arow) * FPK + k0 + GBK + ak;
            a0g = *(const float4*)arp;
            a1g = *(const float4*)(arp + 4);
            b0g = *(const float4*)(B + (size_t)(k0 + GBK + brow) * FPN + bn + bcol);
            b1g = *(const float4*)(B + (size_t)(k0 + GBK + brow) * FPN + bn + bcol + 4);
        }

        const float* Asp = As[p];
        const float* Bsp = Bs[p];
#pragma unroll
        for (int kk = 0; kk < GBK; kk++) {
            float4 a0 = *(const float4*)&Asp[kk * GBM + ty * 4];
            float4 a1 = *(const float4*)&Asp[kk * GBM + 64 + ty * 4];
            ulonglong2 b0 = *(const ulonglong2*)&Bsp[kk * 128 + tx * 4];
            ulonglong2 b1 = *(const ulonglong2*)&Bsp[kk * 128 + 64 + tx * 4];
            ull b2[4] = {b0.x, b0.y, b1.x, b1.y};
            ull aa[8] = {pk2(a0.x, a0.x), pk2(a0.y, a0.y), pk2(a0.z, a0.z), pk2(a0.w, a0.w),
                         pk2(a1.x, a1.x), pk2(a1.y, a1.y), pk2(a1.z, a1.z), pk2(a1.w, a1.w)};
#pragma unroll
            for (int i = 0; i < 8; i++)
#pragma unroll
                for (int j = 0; j < 4; j++)
                    acc2[i][j] = fma2(aa[i], b2[j], acc2[i][j]);
        }

        if (has_next) {
            const int q = p ^ 1;
            As[q][(ak + 0) * GBM + arow] = a0g.x;
            As[q][(ak + 1) * GBM + arow] = a0g.y;
            As[q][(ak + 2) * GBM + arow] = a0g.z;
            As[q][(ak + 3) * GBM + arow] = a0g.w;
            As[q][(ak + 4) * GBM + arow] = a1g.x;
            As[q][(ak + 5) * GBM + arow] = a1g.y;
            As[q][(ak + 6) * GBM + arow] = a1g.z;
            As[q][(ak + 7) * GBM + arow] = a1g.w;
            *(float4*)&Bs[q][brow * 128 + bcol] = b0g;
            *(float4*)&Bs[q][brow * 128 + bcol + 4] = b1g;
            __syncthreads();
            p = q;
        }
    }

#pragma unroll
    for (int i = 0; i < 8; i++) {
        const int row = bm + ((i < 4) ? (ty * 4 + i) : (64 + ty * 4 + i - 4));
        float vlo[4], vhi[4];
        {
            float2 v0 = upk2(acc2[i][0]);
            float2 v1 = upk2(acc2[i][1]);
            vlo[0] = v0.x; vlo[1] = v0.y; vlo[2] = v1.x; vlo[3] = v1.y;
            float2 v2 = upk2(acc2[i][2]);
            float2 v3 = upk2(acc2[i][3]);
            vhi[0] = v2.x; vhi[1] = v2.y; vhi[2] = v3.x; vhi[3] = v3.y;
        }
#pragma unroll
        for (int j = 0; j < 4; j++) {
            const int clo = bn + tx * 4 + j;
            const int chi = bn + 64 + tx * 4 + j;
            float zl = vlo[j], zh = vhi[j];
            if (w == 0)      { zl *= qscale; zh *= qscale; }
            else if (w == 3) {
                zl = 1.f / (1.f + __expf(-(zl + bg[clo])));
                zh = 1.f / (1.f + __expf(-(zh + bg[chi])));
            }
            vlo[j] = zl; vhi[j] = zh;
        }
        {
            __half2 h0 = __floats2half2_rn(vlo[0], vlo[1]);
            __half2 h1 = __floats2half2_rn(vlo[2], vlo[3]);
            uint2 wv; wv.x = *(unsigned*)&h0; wv.y = *(unsigned*)&h1;
            *(uint2*)(C + (size_t)row * FPN + bn + tx * 4) = wv;
            __half2 h2 = __floats2half2_rn(vhi[0], vhi[1]);
            __half2 h3 = __floats2half2_rn(vhi[2], vhi[3]);
            uint2 wh; wh.x = *(unsigned*)&h2; wh.y = *(unsigned*)&h3;
            *(uint2*)(C + (size_t)row * FPN + bn + 64 + tx * 4) = wh;
        }
    }
}

// ---------------------------------------------------------------------------
// fp32 SGEMM v6 for output projection (N=128, K=256) — unchanged.
// ---------------------------------------------------------------------------
__global__ __launch_bounds__(256, 2)
void sgemm6(const float* __restrict__ A, const float* __restrict__ B,
            float* __restrict__ C, int M, int N, int K,
            const float* __restrict__ evec)
{
    __shared__ float As[2][GBK * GBM];
    __shared__ float Bs[2][GBK * GBM];

    const int t  = threadIdx.x;
    const int bm = blockIdx.y * GBM;
    const int bn = blockIdx.x * 128;

    const int arow = t >> 1;
    const int ak   = (t & 1) * 8;
    const int brow = t >> 4;
    const int bcol = (t & 15) * 8;

    const int tx = t & 15;
    const int ty = t >> 4;

    ull acc2[8][4];
#pragma unroll
    for (int i = 0; i < 8; i++)
#pragma unroll
        for (int j = 0; j < 4; j++) acc2[i][j] = 0ULL;

    {
        const float* arp = A + (size_t)(bm + arow) * K + ak;
        float4 a0 = *(const float4*)arp;
        float4 a1 = *(const float4*)(arp + 4);
        As[0][(ak + 0) * GBM + arow] = a0.x;
        As[0][(ak + 1) * GBM + arow] = a0.y;
        As[0][(ak + 2) * GBM + arow] = a0.z;
        As[0][(ak + 3) * GBM + arow] = a0.w;
        As[0][(ak + 4) * GBM + arow] = a1.x;
        As[0][(ak + 5) * GBM + arow] = a1.y;
        As[0][(ak + 6) * GBM + arow] = a1.z;
        As[0][(ak + 7) * GBM + arow] = a1.w;
        *(float4*)&Bs[0][brow * 128 + bcol] =
            *(const float4*)(B + (size_t)brow * N + bn + bcol);
        *(float4*)&Bs[0][brow * 128 + bcol + 4] =
            *(const float4*)(B + (size_t)brow * N + bn + bcol + 4);
    }
    __syncthreads();

    int p = 0;
    for (int k0 = 0; k0 < K; k0 += GBK) {
        const bool has_next = (k0 + GBK) < K;
        float4 a0g, a1g, b0g, b1g;
        if (has_next) {
            const float* arp = A + (size_t)(bm + arow) * K + k0 + GBK + ak;
            a0g = *(const float4*)arp;
            a1g = *(const float4*)(arp + 4);
            b0g = *(const float4*)(B + (size_t)(k0 + GBK + brow) * N + bn + bcol);
            b1g = *(const float4*)(B + (size_t)(k0 + GBK + brow) * N + bn + bcol + 4);
        }

        const float* Asp = As[p];
        const float* Bsp = Bs[p];
#pragma unroll
        for (int kk = 0; kk < GBK; kk++) {
            float4 a0 = *(const float4*)&Asp[kk * GBM + ty * 4];
            float4 a1 = *(const float4*)&Asp[kk * GBM + 64 + ty * 4];
            ulonglong2 b0 = *(const ulonglong2*)&Bsp[kk * 128 + tx * 4];
            ulonglong2 b1 = *(const ulonglong2*)&Bsp[kk * 128 + 64 + tx * 4];
            ull b2[4] = {b0.x, b0.y, b1.x, b1.y};
            ull aa[8] = {pk2(a0.x, a0.x), pk2(a0.y, a0.y), pk2(a0.z, a0.z), pk2(a0.w, a0.w),
                         pk2(a1.x, a1.x), pk2(a1.y, a1.y), pk2(a1.z, a1.z), pk2(a1.w, a1.w)};
#pragma unroll
            for (int i = 0; i < 8; i++)
#pragma unroll
                for (int j = 0; j < 4; j++)
                    acc2[i][j] = fma2(aa[i], b2[j], acc2[i][j]);
        }

        if (has_next) {
            const int q = p ^ 1;
            As[q][(ak + 0) * GBM + arow] = a0g.x;
            As[q][(ak + 1) * GBM + arow] = a0g.y;
            As[q][(ak + 2) * GBM + arow] = a0g.z;
            As[q][(ak + 3) * GBM + arow] = a0g.w;
            As[q][(ak + 4) * GBM + arow] = a1g.x;
            As[q][(ak + 5) * GBM + arow] = a1g.y;
            As[q][(ak + 6) * GBM + arow] = a1g.z;
            As[q][(ak + 7) * GBM + arow] = a1g.w;
            *(float4*)&Bs[q][brow * 128 + bcol] = b0g;
            *(float4*)&Bs[q][brow * 128 + bcol + 4] = b1g;
            __syncthreads();
            p = q;
        }
    }

#pragma unroll
    for (int i = 0; i < 8; i++) {
        const int row = bm + ((i < 4) ? (ty * 4 + i) : (64 + ty * 4 + i - 4));
        float vlo[4], vhi[4];
        {
            float2 v0 = upk2(acc2[i][0]);
            float2 v1 = upk2(acc2[i][1]);
            vlo[0] = v0.x; vlo[1] = v0.y; vlo[2] = v1.x; vlo[3] = v1.y;
            float2 v2 = upk2(acc2[i][2]);
            float2 v3 = upk2(acc2[i][3]);
            vhi[0] = v2.x; vhi[1] = v2.y; vhi[2] = v3.x; vhi[3] = v3.y;
        }
#pragma unroll
        for (int j = 0; j < 4; j++) {
            vlo[j] += evec[bn + tx * 4 + j];
            vhi[j] += evec[bn + 64 + tx * 4 + j];
        }
        *(float4*)(C + (size_t)row * N + bn + tx * 4) =
            make_float4(vlo[0], vlo[1], vlo[2], vlo[3]);
        *(float4*)(C + (size_t)row * N + bn + 64 + tx * 4) =
            make_float4(vhi[0], vhi[1], vhi[2], vhi[3]);
    }
}

// ---------------------------------------------------------------------------
// Attention v10: HMMA (mma.sync m16n8k16) flash kernel.
// Block (h, s, qh): 128 q x 256 k; 8 warps, warp w owns q rows [16w,16w+16).
// Online softmax over two 128-k chunks; S C-frags -> P A-frags in registers.
// smem: Qs[128][40]h @0 (10240B) | Ks[256][40]h @10240 (20480B) |
//       Vt[32][264]h @30720 (16896B) | addm[256]f @47616 (1024B). Total 48640.
// ---------------------------------------------------------------------------
#define QS_STR 40
#define KS_STR 40
#define VT_STR 264
#define AT_SMEM 48640

__global__ __launch_bounds__(256, 2)
void attn10(const __half* __restrict__ Q, const __half* __restrict__ Km,
            const __half* __restrict__ V, const __half* __restrict__ G,
            const __half* __restrict__ biasH, const void* __restrict__ mask,
            float* __restrict__ O)
{
    extern __shared__ char smraw[];
    __half* Qs   = (__half*)smraw;                 // [128][40]
    __half* Ks   = (__half*)(smraw + 10240);       // [256][40]
    __half* Vt   = (__half*)(smraw + 30720);       // [32][264]  (c-major)
    float*  addm = (float*)(smraw + 47616);        // [256]

    const int h  = blockIdx.x;
    const int s  = blockIdx.y;
    const int qh = blockIdx.z;
    const int t  = threadIdx.x;
    const int w  = t >> 5;
    const int lane = t & 31;
    const int r  = lane >> 2;      // 0..7
    const int j  = lane & 3;       // 0..3

    // ---- stage Q: Qs[q][c] ----
    {
        const int q = t >> 1, c0 = (t & 1) * 16;
        const uint4* src = (const uint4*)(Q + ((size_t)(s * S_DIM + qh * 128 + q)) * CQK + h * CH + c0);
        *(uint4*)&Qs[q * QS_STR + c0]     = src[0];
        *(uint4*)&Qs[q * QS_STR + c0 + 8] = src[1];
    }
    // ---- stage K: Ks[k][c] ----
    {
        const int k = t;
        const uint4* src = (const uint4*)(Km + ((size_t)(s * S_DIM + k)) * CQK + h * CH);
        *(uint4*)&Ks[k * KS_STR]      = src[0];
        *(uint4*)&Ks[k * KS_STR + 8]  = src[1];
        *(uint4*)&Ks[k * KS_STR + 16] = src[2];
        *(uint4*)&Ks[k * KS_STR + 24] = src[3];
    }
    // ---- stage V transposed: Vt[c][k] ----
    {
        const int k = t;
        const __half* src = V + ((size_t)(s * S_DIM + k)) * CQK + h * CH;
        uint4 w0 = *(const uint4*)src;
        uint4 w1 = *(const uint4*)(src + 8);
        uint4 w2 = *(const uint4*)(src + 16);
        uint4 w3 = *(const uint4*)(src + 24);
        const __half* hv0 = (const __half*)&w0;
        const __half* hv1 = (const __half*)&w1;
        const __half* hv2 = (const __half*)&w2;
        const __half* hv3 = (const __half*)&w3;
#pragma unroll
        for (int c = 0; c < 8; c++) {
            Vt[(c)      * VT_STR + k] = hv0[c];
            Vt[(c + 8)  * VT_STR + k] = hv1[c];
            Vt[(c + 16) * VT_STR + k] = hv2[c];
            Vt[(c + 24) * VT_STR + k] = hv3[c];
        }
    }
    // ---- mask -> additive ----
    {
        const int idx = s * S_DIM + t;
        const int code = g_f_float ? 2 : (g_f_u8 ? 1 : 0);
        bool mv;
        if (code == 2)      mv = ((const float*)mask)[idx] != 0.f;
        else if (code == 1) mv = ((const unsigned char*)mask)[idx] != 0;
        else                mv = ((const int*)mask)[idx] != 0;
        addm[t] = mv ? 0.f : -1e30f;
    }
    __syncthreads();

    // ---- A fragments of Q (held for whole kernel): 2 c-steps ----
    const int q0 = w * 16;
    uint_t afr[2][4];
#pragma unroll
    for (int cs = 0; cs < 2; cs++) {
        const int c = cs * 16 + 2 * j;
        afr[cs][0] = *(const uint_t*)&Qs[(q0 + r)     * QS_STR + c];
        afr[cs][1] = *(const uint_t*)&Qs[(q0 + r + 8) * QS_STR + c];
        afr[cs][2] = *(const uint_t*)&Qs[(q0 + r)     * QS_STR + c + 8];
        afr[cs][3] = *(const uint_t*)&Qs[(q0 + r + 8) * QS_STR + c + 8];
    }

    const int qg0 = qh * 128 + q0 + r;        // global bias row for row r
    const __half* bbase = biasH + ((size_t)h * S_DIM) * S_DIM;

    float mrow[2] = {-INFINITY, -INFINITY};
    float lrow[2] = {0.f, 0.f};
    float oacc[4][4];
#pragma unroll
    for (int i = 0; i < 4; i++)
#pragma unroll
        for (int u = 0; u < 4; u++) oacc[i][u] = 0.f;

#pragma unroll
    for (int ch = 0; ch < 2; ch++) {
        const int kbase = ch * 128;

        // ---- S = Q.K^T for this chunk: 16 n8-tiles ----
        float sc[16][4];
#pragma unroll
        for (int tt = 0; tt < 16; tt++) {
            const int n0 = kbase + tt * 8;
            float d0 = 0.f, d1 = 0.f, d2 = 0.f, d3 = 0.f;
#pragma unroll
            for (int cs = 0; cs < 2; cs++) {
                const int c = cs * 16 + 2 * j;
                uint_t b0 = *(const uint_t*)&Ks[(n0 + r) * KS_STR + c];
                uint_t b1 = *(const uint_t*)&Ks[(n0 + r) * KS_STR + c + 8];
                mma16816(d0, d1, d2, d3,
                         afr[cs][0], afr[cs][1], afr[cs][2], afr[cs][3], b0, b1);
            }
            // bias + mask
            const int kc = n0 + 2 * j;
            float2 am = *(const float2*)&addm[kc];
            uint_t bw0 = *(const uint_t*)(bbase + (size_t)qg0 * S_DIM + kc);
            uint_t bw1 = *(const uint_t*)(bbase + (size_t)(qg0 + 8) * S_DIM + kc);
            float2 bf0 = __half22float2(*(__half2*)&bw0);
            float2 bf1 = __half22float2(*(__half2*)&bw1);
            sc[tt][0] = d0 + bf0.x + am.x;
            sc[tt][1] = d1 + bf0.y + am.y;
            sc[tt][2] = d2 + bf1.x + am.x;
            sc[tt][3] = d3 + bf1.y + am.y;
        }

        // ---- chunk row max (local + quad shuffle) ----
        float cm0 = sc[0][0], cm1 = sc[0][2];
#pragma unroll
        for (int tt = 0; tt < 16; tt++) {
            cm0 = fmaxf(cm0, fmaxf(sc[tt][0], sc[tt][1]));
            cm1 = fmaxf(cm1, fmaxf(sc[tt][2], sc[tt][3]));
        }
        cm0 = fmaxf(cm0, __shfl_xor_sync(0xFFFFFFFFu, cm0, 1));
        cm0 = fmaxf(cm0, __shfl_xor_sync(0xFFFFFFFFu, cm0, 2));
        cm1 = fmaxf(cm1, __shfl_xor_sync(0xFFFFFFFFu, cm1, 1));
        cm1 = fmaxf(cm1, __shfl_xor_sync(0xFFFFFFFFu, cm1, 2));

        const float mn0 = fmaxf(mrow[0], cm0);
        const float mn1 = fmaxf(mrow[1], cm1);
        const float sc0 = __expf(mrow[0] - mn0);   // 0 on first chunk
        const float sc1 = __expf(mrow[1] - mn1);
        mrow[0] = mn0; mrow[1] = mn1;
        lrow[0] *= sc0; lrow[1] *= sc1;
#pragma unroll
        for (int i = 0; i < 4; i++) {
            oacc[i][0] *= sc0; oacc[i][1] *= sc0;
            oacc[i][2] *= sc1; oacc[i][3] *= sc1;
        }

        // ---- exp + l accumulation ----
        float ls0 = 0.f, ls1 = 0.f;
#pragma unroll
        for (int tt = 0; tt < 16; tt++) {
            sc[tt][0] = __expf(sc[tt][0] - mn0);
            sc[tt][1] = __expf(sc[tt][1] - mn0);
            sc[tt][2] = __expf(sc[tt][2] - mn1);
            sc[tt][3] = __expf(sc[tt][3] - mn1);
            ls0 += sc[tt][0] + sc[tt][1];
            ls1 += sc[tt][2] + sc[tt][3];
        }
        ls0 += __shfl_xor_sync(0xFFFFFFFFu, ls0, 1);
        ls0 += __shfl_xor_sync(0xFFFFFFFFu, ls0, 2);
        ls1 += __shfl_xor_sync(0xFFFFFFFFu, ls1, 1);
        ls1 += __shfl_xor_sync(0xFFFFFFFFu, ls1, 2);
        lrow[0] += ls0; lrow[1] += ls1;

        // ---- O += P.V : 8 k16-steps x 4 c-tiles ----
#pragma unroll
        for (int ks = 0; ks < 8; ks++) {
            // P A-frag from S C-frags of tiles 2ks, 2ks+1
            __half2 p0 = __floats2half2_rn(sc[2 * ks][0],     sc[2 * ks][1]);
            __half2 p1 = __floats2half2_rn(sc[2 * ks][2],     sc[2 * ks][3]);
            __half2 p2 = __floats2half2_rn(sc[2 * ks + 1][0], sc[2 * ks + 1][1]);
            __half2 p3 = __floats2half2_rn(sc[2 * ks + 1][2], sc[2 * ks + 1][3]);
            uint_t pa0 = *(uint_t*)&p0;
            uint_t pa1 = *(uint_t*)&p1;
            uint_t pa2 = *(uint_t*)&p2;
            uint_t pa3 = *(uint_t*)&p3;
            const int kk = kbase + ks * 16 + 2 * j;
#pragma unroll
            for (int ct = 0; ct < 4; ct++) {
                const int cc = ct * 8 + r;
                uint_t b0 = *(const uint_t*)&Vt[cc * VT_STR + kk];
                uint_t b1 = *(const uint_t*)&Vt[cc * VT_STR + kk + 8];
                mma16816(oacc[ct][0], oacc[ct][1], oacc[ct][2], oacc[ct][3],
                         pa0, pa1, pa2, pa3, b0, b1);
            }
        }
    }

    // ---- epilogue: normalize + gate + store ----
    {
        const float ri0 = 1.f / lrow[0];
        const float ri1 = 1.f / lrow[1];
        const size_t row0 = (size_t)(s * S_DIM + qh * 128 + q0 + r);
        const size_t row1 = row0 + 8;
#pragma unroll
        for (int ct = 0; ct < 4; ct++) {
            const int cc = ct * 8 + 2 * j;
            uint_t g0 = *(const uint_t*)(G + row0 * CQK + h * CH + cc);
            uint_t g1 = *(const uint_t*)(G + row1 * CQK + h * CH + cc);
            float2 gf0 = __half22float2(*(__half2*)&g0);
            float2 gf1 = __half22float2(*(__half2*)&g1);
            float2 o0 = make_float2(oacc[ct][0] * ri0 * gf0.x,
                                    oacc[ct][1] * ri0 * gf0.y);
            float2 o1 = make_float2(oacc[ct][2] * ri1 * gf1.x,
                                    oacc[ct][3] * ri1 * gf1.y);
            *(float2*)(O + row0 * CQK + h * CH + cc) = o0;
            *(float2*)(O + row1 * CQK + h * CH + cc) = o1;
        }
    }
}

// ---------------------------------------------------------------------------
// Launch
// ---------------------------------------------------------------------------
extern "C" void kernel_launch(void* const* d_in, const int* in_sizes, int n_in,
                              void* d_out, int out_size)
{
    const float* x    = (const float*)d_in[0];
    const float* bias = (const float*)d_in[1];
    const void*  mask = d_in[2];
    const float* Wq   = (const float*)d_in[3];
    const float* Wk   = (const float*)d_in[4];
    const float* Wv   = (const float*)d_in[5];
    const float* Wo   = (const float*)d_in[6];
    const float* bo   = (const float*)d_in[7];
    const float* Wg   = (const float*)d_in[8];
    const float* bg   = (const float*)d_in[9];
    float* out = (float*)d_out;

    void *pQ, *pK, *pV, *pG, *pO, *pB;
    cudaGetSymbolAddress(&pQ, g_QH);
    cudaGetSymbolAddress(&pK, g_KH);
    cudaGetSymbolAddress(&pV, g_VH);
    cudaGetSymbolAddress(&pG, g_GH);
    cudaGetSymbolAddress(&pO, g_O);
    cudaGetSymbolAddress(&pB, g_biasH);
    __half* Qb = (__half*)pQ; __half* Kb = (__half*)pK; __half* Vb = (__half*)pV;
    __half* Gb = (__half*)pG; float* Ob = (float*)pO; __half* biasH = (__half*)pB;

    const float qscale = 0.17677669529663687f;   // 1/sqrt(32)

    init_flags_kernel<<<1, 1>>>();
    detect_mask_kernel<<<64, 256>>>((const unsigned char*)mask, S_DIM * S_DIM);
    conv_bias_kernel<<<(NH * S_DIM * S_DIM / 4) / 256, 256>>>(bias, biasH);

    fused_proj<<<dim3(8, NROWS / GBM), 256>>>(x, Wq, Wk, Wv, Wg,
                                              Qb, Kb, Vb, Gb, bg, qscale);

    cudaFuncSetAttribute(attn10, cudaFuncAttributeMaxDynamicSharedMemorySize, AT_SMEM);
    attn10<<<dim3(NH, S_DIM, 2), 256, AT_SMEM>>>(Qb, Kb, Vb, Gb, biasH, mask, Ob);

    sgemm6<<<dim3(1, NROWS / GBM), 256>>>(Ob, Wo, out, NROWS, CIN, CQK, bo);
}